// round 9
// baseline (speedup 1.0000x reference)
#include <cuda_runtime.h>
#include <cuda_fp16.h>
#include <cstdint>
#include <math.h>

// ---------------- problem constants ----------------
#define NN   2048
#define BB   16
#define DD   64
#define DIN  66
#define EMB  16
#define OG   128
#define OU   64
#define XCOLS (BB*DIN)   // 1056
#define XPAD  1152

// ---------------- device scratch ----------------
__device__ float g_A   [(size_t)NN*NN];
__device__ unsigned char g_mask[(size_t)NN*NN];
__device__ float g_Wg  [(size_t)NN*2*DIN*OG];
__device__ float g_Wu  [(size_t)NN*2*DIN*OU];
__device__ float g_inpT[(size_t)NN*XCOLS];
__device__ float g_candT[(size_t)NN*XCOLS];
__device__ float g_xg1T[(size_t)NN*XPAD];
__device__ float g_xg2T[(size_t)NN*XPAD];
__device__ float g_r   [(size_t)BB*NN*DD];
__device__ float g_h   [(size_t)BB*NN*DD];
__device__ __half g_h16 [(size_t)BB*NN*DD];
__device__ __half g_shi[(size_t)NN*NN];
__device__ __half g_slo[(size_t)NN*NN];
__device__ __half g_xinhi[(size_t)NN*XPAD];
__device__ __half g_xinlo[(size_t)NN*XPAD];
__device__ __half g_xcahi[(size_t)NN*XPAD];
__device__ __half g_xcalo[(size_t)NN*XPAD];
__device__ __half g_ac[(size_t)BB*NN*NN];
__device__ __half g_ad[(size_t)BB*NN*NN];
__device__ __half g_wc[(size_t)NN*NN];
__device__ __half g_wd[(size_t)NN*NN];

// ---------------- asm helpers ----------------
__device__ __forceinline__ uint32_t s2u(const void* p) {
    return (uint32_t)__cvta_generic_to_shared(p);
}
__device__ __forceinline__ void cp16(uint32_t dst, const void* src) {
    asm volatile("cp.async.cg.shared.global [%0], [%1], 16;" :: "r"(dst), "l"(src));
}
__device__ __forceinline__ void cpcommit() { asm volatile("cp.async.commit_group;"); }
__device__ __forceinline__ void ldsm4(uint32_t* r, uint32_t addr) {
    asm volatile("ldmatrix.sync.aligned.m8n8.x4.shared.b16 {%0,%1,%2,%3}, [%4];"
        : "=r"(r[0]), "=r"(r[1]), "=r"(r[2]), "=r"(r[3]) : "r"(addr));
}
__device__ __forceinline__ void ldsm4t(uint32_t* r, uint32_t addr) {
    asm volatile("ldmatrix.sync.aligned.m8n8.x4.trans.shared.b16 {%0,%1,%2,%3}, [%4];"
        : "=r"(r[0]), "=r"(r[1]), "=r"(r[2]), "=r"(r[3]) : "r"(addr));
}
__device__ __forceinline__ void mma16816(float* c, const uint32_t* a, uint32_t b0, uint32_t b1) {
    asm volatile(
        "mma.sync.aligned.m16n8k16.row.col.f32.f16.f16.f32 "
        "{%0,%1,%2,%3}, {%4,%5,%6,%7}, {%8,%9}, {%0,%1,%2,%3};"
        : "+f"(c[0]), "+f"(c[1]), "+f"(c[2]), "+f"(c[3])
        : "r"(a[0]), "r"(a[1]), "r"(a[2]), "r"(a[3]), "r"(b0), "r"(b1));
}
__device__ __forceinline__ float fexp(float x) {
    float t = fmaxf(x * 1.4426950408889634f, -125.f);
    int   ni = __float2int_rn(t);
    float f  = t - (float)ni;
    float p = 0.00133335581f;
    p = fmaf(p, f, 0.00961812910f);
    p = fmaf(p, f, 0.05550410866f);
    p = fmaf(p, f, 0.24022650696f);
    p = fmaf(p, f, 0.69314718056f);
    p = fmaf(p, f, 1.0f);
    return p * __int_as_float((ni + 127) << 23);
}
__device__ __forceinline__ uint32_t packh2(float a, float b) {
    __half2 h = __floats2half2_rn(a, b);
    return *(uint32_t*)&h;
}

// ---------------- A = E E^T + sign mask ----------------
__global__ void k_embed_outer(const float* __restrict__ E) {
    __shared__ float En[16][17], Em[16][17];
    int tx = threadIdx.x, ty = threadIdx.y;
    En[ty][tx] = E[((size_t)blockIdx.y*16 + ty)*EMB + tx];
    Em[ty][tx] = E[((size_t)blockIdx.x*16 + ty)*EMB + tx];
    __syncthreads();
    float s = 0.f;
#pragma unroll
    for (int e = 0; e < 16; e++) s += En[ty][e] * Em[tx][e];
    size_t idx = ((size_t)blockIdx.y*16 + ty)*NN + blockIdx.x*16 + tx;
    g_A[idx] = s;
    g_mask[idx] = (s > 0.f) ? 1 : ((s < 0.f) ? 2 : 0);
}

// ---------------- S softmax: relu(A) -> fp16 hi/lo ----------------
__global__ void k_srowsoftmax() {
    __shared__ float buf[NN];
    __shared__ float red[256];
    int row = blockIdx.x;
    int tid = threadIdx.x;
    const float* in = g_A + (size_t)row*NN;
    float mx = -1e30f;
    for (int i = tid; i < NN; i += 256) {
        float v = in[i];
        v = v > 0.f ? v : 0.f;
        buf[i] = v;
        mx = fmaxf(mx, v);
    }
    red[tid] = mx; __syncthreads();
    for (int s = 128; s > 0; s >>= 1) {
        if (tid < s) red[tid] = fmaxf(red[tid], red[tid+s]);
        __syncthreads();
    }
    mx = red[0];
    __syncthreads();
    float sum = 0.f;
    for (int i = tid; i < NN; i += 256) {
        float e = fexp(buf[i] - mx);
        buf[i] = e;
        sum += e;
    }
    red[tid] = sum; __syncthreads();
    for (int s = 128; s > 0; s >>= 1) {
        if (tid < s) red[tid] += red[tid+s];
        __syncthreads();
    }
    float inv = 1.0f / red[0];
    for (int i = tid; i < NN; i += 256) {
        float v = buf[i] * inv;
        __half hi = __float2half_rn(v);
        g_shi[(size_t)row*NN + i] = hi;
        g_slo[(size_t)row*NN + i] = __float2half_rn(v - __half2float(hi));
    }
}

// ---------------- per-node weights, tiled ----------------
__global__ void __launch_bounds__(256) k_mkW2(const float* __restrict__ E,
                                              const float* __restrict__ pool,
                                              int per_e, float* __restrict__ W) {
    __shared__ __align__(16) float Es[16][128];
    __shared__ __align__(16) float Ps[16][128];
    int tid = threadIdx.x;
    int j0 = blockIdx.x*128, m0 = blockIdx.y*128;
    {
        int r = tid >> 1, e0 = (tid & 1)*8;
        float4 a = *(const float4*)&E[(size_t)(m0+r)*EMB + e0];
        float4 b = *(const float4*)&E[(size_t)(m0+r)*EMB + e0 + 4];
        Es[e0+0][r]=a.x; Es[e0+1][r]=a.y; Es[e0+2][r]=a.z; Es[e0+3][r]=a.w;
        Es[e0+4][r]=b.x; Es[e0+5][r]=b.y; Es[e0+6][r]=b.z; Es[e0+7][r]=b.w;
    }
    {
        int e = tid >> 4, c0 = (tid & 15)*8;
        float4 a = *(const float4*)&pool[(size_t)e*per_e + j0 + c0];
        float4 b = *(const float4*)&pool[(size_t)e*per_e + j0 + c0 + 4];
        *(float4*)&Ps[e][c0]   = a;
        *(float4*)&Ps[e][c0+4] = b;
    }
    __syncthreads();
    int row0 = (tid/16)*8, col0 = (tid%16)*8;
    float acc[8][8] = {};
#pragma unroll
    for (int k = 0; k < 16; k++) {
        float av[8], bv[8];
        float4 t;
        t = *(const float4*)&Es[k][row0];   av[0]=t.x; av[1]=t.y; av[2]=t.z; av[3]=t.w;
        t = *(const float4*)&Es[k][row0+4]; av[4]=t.x; av[5]=t.y; av[6]=t.z; av[7]=t.w;
        t = *(const float4*)&Ps[k][col0];   bv[0]=t.x; bv[1]=t.y; bv[2]=t.z; bv[3]=t.w;
        t = *(const float4*)&Ps[k][col0+4]; bv[4]=t.x; bv[5]=t.y; bv[6]=t.z; bv[7]=t.w;
#pragma unroll
        for (int i = 0; i < 8; i++)
#pragma unroll
            for (int j = 0; j < 8; j++) acc[i][j] += av[i]*bv[j];
    }
#pragma unroll
    for (int i = 0; i < 8; i++) {
        size_t ro = (size_t)(m0 + row0 + i)*per_e + j0 + col0;
        *(float4*)&W[ro]   = make_float4(acc[i][0], acc[i][1], acc[i][2], acc[i][3]);
        *(float4*)&W[ro+4] = make_float4(acc[i][4], acc[i][5], acc[i][6], acc[i][7]);
    }
}

// ---------------- concat ----------------
__global__ void k_concat(const float* __restrict__ x, const float* __restrict__ state) {
    int idx = blockIdx.x*256 + threadIdx.x;
    if (idx >= NN*XCOLS) return;
    int n = idx / XCOLS;
    int rem = idx % XCOLS;
    int b = rem / DIN, i = rem % DIN;
    float v;
    if (i < 2) v = x[((size_t)b*NN + n)*2 + i];
    else       v = state[((size_t)b*NN + n)*DD + (i-2)];
    g_inpT[idx] = v;
    __half hi = __float2half_rn(v);
    __half lo = __float2half_rn(v - __half2float(hi));
    size_t pidx = (size_t)n*XPAD + rem;
    g_xinhi[pidx] = hi; g_xinlo[pidx] = lo;
    if (i < 2) {
        g_candT[idx] = v;
        g_xcahi[pidx] = hi; g_xcalo[pidx] = lo;
    }
}

// ---------------- xg = S @ X on HMMA (3 passes) ----------------
#define SX_NSTG 3
__global__ void __launch_bounds__(256, 2) k_sx_mma(int which) {
    extern __shared__ __align__(16) __half dsm[];
    const __half* Bhi = which ? g_xcahi : g_xinhi;
    const __half* Blo = which ? g_xcalo : g_xinlo;
    float* C = which ? g_xg2T : g_xg1T;

    const int tid = threadIdx.x;
    const int n0 = blockIdx.x*128;
    const int m0 = blockIdx.y*128;
    uint32_t su = s2u(dsm);

    const int rowA = tid >> 1, ap0 = (tid & 1)*2;
    const int rowB = tid >> 3, bp0 = (tid & 7)*2;
    const size_t aRow = (size_t)(m0 + rowA)*NN;
    uint32_t dA[2], dB[2];
#pragma unroll
    for (int t = 0; t < 2; t++) {
        int ch = ap0 + t;
        dA[t] = rowA*64 + ((ch ^ ((rowA>>1)&3)) << 4);
        int cb = bp0 + t;
        dB[t] = 16384 + rowB*256 + ((cb ^ (rowB&7)) << 4);
    }

    auto issue = [&](int c, int s) {
        uint32_t base = su + s*32768;
#pragma unroll
        for (int t = 0; t < 2; t++) {
            int ch = ap0 + t;
            cp16(base + dA[t],        g_shi + aRow + c*32 + ch*8);
            cp16(base + 8192 + dA[t], g_slo + aRow + c*32 + ch*8);
        }
#pragma unroll
        for (int t = 0; t < 2; t++) {
            int cb = bp0 + t;
            size_t bo = (size_t)(c*32 + rowB)*XPAD + n0 + cb*8;
            cp16(base + dB[t],        Bhi + bo);
            cp16(base + 8192 + dB[t], Blo + bo);
        }
        cpcommit();
    };

    const int lane = tid & 31, wid = tid >> 5;
    const int wm = (wid & 1)*64, wn = (wid >> 1)*32;
    const int frow = ((lane>>3)&1)*8 + (lane&7);
    const int fch  = lane >> 4;

    float acc[4][4][4] = {};
    issue(0, 0); issue(1, 1);
    const int NC = NN/32;
    for (int c = 0; c < NC; c++) {
        int s = c % SX_NSTG;
        if (c + 1 < NC) asm volatile("cp.async.wait_group 1;" ::: "memory");
        else            asm volatile("cp.async.wait_group 0;" ::: "memory");
        __syncthreads();
        if (c + 2 < NC) issue(c + 2, (c + 2) % SX_NSTG);
        uint32_t base = su + s*32768;
#pragma unroll
        for (int ks = 0; ks < 2; ks++) {
            uint32_t af[4][4], bh[2][4], bl[2][4];
#pragma unroll
            for (int i = 0; i < 4; i++) {
                int row = wm + i*16 + frow;
                int ch = 2*ks + fch;
                ldsm4(af[i], base + row*64 + ((ch ^ ((row>>1)&3)) << 4));
            }
#pragma unroll
            for (int jj = 0; jj < 2; jj++) {
                int krow = ks*16 + frow;
                int ch = (wn >> 3) + jj*2 + fch;
                ldsm4t(bh[jj], base + 16384 + krow*256 + ((ch ^ (krow&7)) << 4));
            }
#pragma unroll
            for (int i = 0; i < 4; i++)
#pragma unroll
                for (int j = 0; j < 4; j++) {
                    int jj = j >> 1, sb = (j & 1)*2;
                    mma16816(acc[i][j], af[i], bh[jj][sb], bh[jj][sb+1]);
                }
#pragma unroll
            for (int jj = 0; jj < 2; jj++) {
                int krow = ks*16 + frow;
                int ch = (wn >> 3) + jj*2 + fch;
                ldsm4t(bl[jj], base + 24576 + krow*256 + ((ch ^ (krow&7)) << 4));
            }
#pragma unroll
            for (int i = 0; i < 4; i++)
#pragma unroll
                for (int j = 0; j < 4; j++) {
                    int jj = j >> 1, sb = (j & 1)*2;
                    mma16816(acc[i][j], af[i], bl[jj][sb], bl[jj][sb+1]);
                }
#pragma unroll
            for (int i = 0; i < 4; i++) {
                int row = wm + i*16 + frow;
                int ch = 2*ks + fch;
                ldsm4(af[i], base + 8192 + row*64 + ((ch ^ ((row>>1)&3)) << 4));
            }
#pragma unroll
            for (int i = 0; i < 4; i++)
#pragma unroll
                for (int j = 0; j < 4; j++) {
                    int jj = j >> 1, sb = (j & 1)*2;
                    mma16816(acc[i][j], af[i], bh[jj][sb], bh[jj][sb+1]);
                }
        }
    }
    const int r = lane >> 2, cq = (lane & 3)*2;
#pragma unroll
    for (int i = 0; i < 4; i++) {
        int r0 = m0 + wm + i*16 + r;
#pragma unroll
        for (int j = 0; j < 4; j++) {
            int cc = n0 + wn + j*8 + cq;
            *(float2*)&C[(size_t)r0*XPAD + cc]     = make_float2(acc[i][j][0], acc[i][j][1]);
            *(float2*)&C[(size_t)(r0+8)*XPAD + cc] = make_float2(acc[i][j][2], acc[i][j][3]);
        }
    }
}

// ---------------- gate apply ----------------
__global__ void k_gate_apply(const float* __restrict__ E, const float* __restrict__ gate_b,
                             const float* __restrict__ state) {
    int n = blockIdx.x;
    int o = threadIdx.x;
    __shared__ float Xs[BB][2*DIN];
    __shared__ float Es[16];
    if (o < 16) Es[o] = E[(size_t)n*EMB + o];
    for (int idx = o; idx < BB*2*DIN; idx += 128) {
        int bb = idx / (2*DIN), i = idx % (2*DIN);
        float v = (i < DIN) ? g_inpT[(size_t)n*XCOLS + bb*DIN + i]
                            : g_xg1T[(size_t)n*XPAD + bb*DIN + (i - DIN)];
        Xs[bb][i] = v;
    }
    __syncthreads();
    float bias = 0.f;
#pragma unroll
    for (int e = 0; e < 16; e++) bias += Es[e] * gate_b[e*OG + o];
    float acc[BB];
#pragma unroll
    for (int bb = 0; bb < BB; bb++) acc[bb] = bias;
    const float* Wn = g_Wg + (size_t)n*(2*DIN*OG);
    for (int i = 0; i < 2*DIN; i++) {
        float w = Wn[(size_t)i*OG + o];
#pragma unroll
        for (int bb = 0; bb < BB; bb++) acc[bb] += Xs[bb][i] * w;
    }
#pragma unroll
    for (int bb = 0; bb < BB; bb++) {
        float v = 1.0f / (1.0f + __expf(-acc[bb]));
        if (o < DD) {
            float st = state[((size_t)bb*NN + n)*DD + o];
            float zs = v * st;
            g_candT[(size_t)n*XCOLS + bb*DIN + 2 + o] = zs;
            __half hi = __float2half_rn(zs);
            size_t pidx = (size_t)n*XPAD + bb*DIN + 2 + o;
            g_xcahi[pidx] = hi;
            g_xcalo[pidx] = __float2half_rn(zs - __half2float(hi));
        } else {
            g_r[((size_t)bb*NN + n)*DD + (o - DD)] = v;
        }
    }
}

// ---------------- update apply: h, h16, out base 0.8h ----------------
__global__ void k_upd_apply(const float* __restrict__ E, const float* __restrict__ upd_b,
                            const float* __restrict__ state, float* __restrict__ out) {
    int n = blockIdx.x;
    int o = threadIdx.x;
    __shared__ float Xs[BB][2*DIN];
    __shared__ float Es[16];
    if (o < 16) Es[o] = E[(size_t)n*EMB + o];
    for (int idx = o; idx < BB*2*DIN; idx += 64) {
        int bb = idx / (2*DIN), i = idx % (2*DIN);
        Xs[bb][i] = (i < DIN) ? g_candT[(size_t)n*XCOLS + bb*DIN + i]
                              : g_xg2T[(size_t)n*XPAD + bb*DIN + (i - DIN)];
    }
    __syncthreads();
    float bias = 0.f;
#pragma unroll
    for (int e = 0; e < 16; e++) bias += Es[e] * upd_b[e*OU + o];
    float acc[BB];
#pragma unroll
    for (int bb = 0; bb < BB; bb++) acc[bb] = bias;
    const float* Wn = g_Wu + (size_t)n*(2*DIN*OU);
    for (int i = 0; i < 2*DIN; i++) {
        float w = Wn[(size_t)i*OU + o];
#pragma unroll
        for (int bb = 0; bb < BB; bb++) acc[bb] += Xs[bb][i] * w;
    }
#pragma unroll
    for (int bb = 0; bb < BB; bb++) {
        float hc = tanhf(acc[bb]);
        size_t ix = ((size_t)bb*NN + n)*DD + o;
        float r = g_r[ix];
        float hv = r * state[ix] + (1.0f - r) * hc;
        g_h[ix] = hv;
        g_h16[ix] = __float2half_rn(hv);
        out[ix] = 0.8f * hv;
    }
}

// ---------------- HHT on HMMA: g_ac/g_ad = mask(.) * (h16 @ h16^T) ----------------
__global__ void __launch_bounds__(256, 2) k_hht_mma() {
    __shared__ __align__(16) __half sA[128*64];
    __shared__ __align__(16) __half sB[128*64];
    const int tid = threadIdx.x;
    const int b = blockIdx.z, m0 = blockIdx.y*128, n0 = blockIdx.x*128;
    uint32_t aU = s2u(sA), bU = s2u(sB);

    const int row = tid >> 1, c0 = (tid & 1)*4;
#pragma unroll
    for (int t = 0; t < 4; t++) {
        int ch = c0 + t;
        uint32_t off = row*128 + ((ch ^ (row&7)) << 4);
        cp16(aU + off, g_h16 + ((size_t)b*NN + m0 + row)*64 + ch*8);
        cp16(bU + off, g_h16 + ((size_t)b*NN + n0 + row)*64 + ch*8);
    }
    cpcommit();
    asm volatile("cp.async.wait_group 0;" ::: "memory");
    __syncthreads();

    const int lane = tid & 31, wid = tid >> 5;
    const int wm = (wid & 1)*64, wn = (wid >> 1)*32;
    const int frow = ((lane>>3)&1)*8 + (lane&7);
    const int fch  = lane >> 4;

    float acc[4][4][4] = {};
#pragma unroll
    for (int ks = 0; ks < 4; ks++) {
        uint32_t af[4][4], bf[2][4];
#pragma unroll
        for (int i = 0; i < 4; i++) {
            int rr = wm + i*16 + frow;
            int ch = 2*ks + fch;
            ldsm4(af[i], aU + rr*128 + ((ch ^ (rr&7)) << 4));
        }
#pragma unroll
        for (int jj = 0; jj < 2; jj++) {
            int rr = wn + jj*16 + frow;
            int ch = 2*ks + fch;
            ldsm4(bf[jj], bU + rr*128 + ((ch ^ (rr&7)) << 4));
        }
#pragma unroll
        for (int i = 0; i < 4; i++)
#pragma unroll
            for (int j = 0; j < 4; j++) {
                int jj = j >> 1, sb = j & 1;
                mma16816(acc[i][j], af[i], bf[jj][sb], bf[jj][sb+2]);
            }
    }
    const int r = lane >> 2, cq = (lane & 3)*2;
#pragma unroll
    for (int i = 0; i < 4; i++) {
        int rbase = m0 + wm + i*16 + r;
#pragma unroll
        for (int j = 0; j < 4; j++) {
            int cc = n0 + wn + j*8 + cq;
#pragma unroll
            for (int hh = 0; hh < 2; hh++) {
                int rr = rbase + hh*8;
                uchar2 mk = *(const uchar2*)&g_mask[(size_t)rr*NN + cc];
                float v0 = acc[i][j][hh*2+0], v1 = acc[i][j][hh*2+1];
                __half2 hc = __floats2half2_rn(mk.x == 1 ? v0 : 0.f, mk.y == 1 ? v1 : 0.f);
                __half2 hd = __floats2half2_rn(mk.x == 2 ? v0 : 0.f, mk.y == 2 ? v1 : 0.f);
                *(__half2*)&g_ac[((size_t)b*NN + rr)*NN + cc] = hc;
                *(__half2*)&g_ad[((size_t)b*NN + rr)*NN + cc] = hd;
            }
        }
    }
}

// ---------------- W (fp32 [k][n]) -> transposed fp16 Wt[n][k] ----------------
__global__ void k_convW(const float* __restrict__ W, int which) {
    __shared__ float t[32][33];
    int tx = threadIdx.x, ty = threadIdx.y;
    int bx = blockIdx.x*32, by = blockIdx.y*32;
    for (int j = 0; j < 32; j += 8)
        t[ty+j][tx] = W[(size_t)(by+ty+j)*NN + bx+tx];
    __syncthreads();
    __half* Wt = (which == 0) ? g_wc : g_wd;
    for (int j = 0; j < 32; j += 8) {
        float v = t[tx][ty+j];
        Wt[(size_t)(bx+ty+j)*NN + by+tx] = __float2half_rn(v);
    }
}

// ---------------- fused flash kernel: softmax(Amask@W) @ h, online over n-tiles ----------------
// CTA: 128 rows (m-tile), 8 warps each owning 16 rows x full 128-col logit tile.
// For each of 16 n-tiles: 64 K-chunks of logits GEMM, then online-softmax update + P@V.
// out += alpha * (P @ h16) / l   via atomicAdd (base 0.8h pre-written).
__global__ void __launch_bounds__(256, 1) k_flash(float* __restrict__ out) {
    extern __shared__ __align__(16) __half fsm[];
    const int tid = threadIdx.x;
    const int m0 = blockIdx.x * 128;
    const int bz = blockIdx.y, b = bz & 15, br = bz >> 4;
    const __half* Am = ((br == 0) ? g_ac : g_ad) + (size_t)b*NN*NN;
    const __half* Wt = (br == 0) ? g_wc : g_wd;
    const __half* Hp = g_h16 + (size_t)b*NN*DD;
    const float alpha = (br == 0) ? -0.1f : 0.1f;
    uint32_t su = s2u(fsm);
    const uint32_t aU = su;                 // 3 x 8KB
    const uint32_t wU = su + 3*8192;        // 3 x 8KB
    const uint32_t vU = su + 6*8192;        // 2 x 16KB

    // loaders
    const int rowA = tid >> 1, ap0 = (tid & 1)*2;
    const size_t aRow = (size_t)(m0 + rowA)*NN;
    uint32_t dA[2];
#pragma unroll
    for (int t = 0; t < 2; t++) {
        int ch = ap0 + t;
        dA[t] = rowA*64 + ((ch ^ ((rowA>>1)&3)) << 4);
    }
    const int rowV = tid >> 1, vc0 = (tid & 1)*4;

    auto issue = [&](int step, int s) {
        int nt = step >> 6, c = step & 63;
#pragma unroll
        for (int t = 0; t < 2; t++) {
            cp16(aU + s*8192 + dA[t], Am + aRow + c*32 + (ap0+t)*8);
            cp16(wU + s*8192 + dA[t], Wt + (size_t)(nt*128 + rowA)*NN + c*32 + (ap0+t)*8);
        }
        if (c == 0) {
            uint32_t vb = vU + (nt & 1)*16384;
            const __half* vsrc = Hp + (size_t)(nt*128 + rowV)*DD;
#pragma unroll
            for (int t = 0; t < 4; t++) {
                int ch = vc0 + t;
                cp16(vb + rowV*128 + ((ch ^ (rowV&7)) << 4), vsrc + ch*8);
            }
        }
        cpcommit();
    };

    const int lane = tid & 31, wid = tid >> 5;
    const int wm = wid*16;
    const int frow = ((lane>>3)&1)*8 + (lane&7);
    const int fch  = lane >> 4;

    float sacc[16][4];
    float oacc[8][4] = {};
    float m0r = -1e30f, m1r = -1e30f, l0 = 0.f, l1 = 0.f;

    issue(0, 0); issue(1, 1);
    const int NSTEP = 16*64;
    for (int step = 0; step < NSTEP; step++) {
        int s = step % 3;
        if (step + 1 < NSTEP) asm volatile("cp.async.wait_group 1;" ::: "memory");
        else                  asm volatile("cp.async.wait_group 0;" ::: "memory");
        __syncthreads();
        if (step + 2 < NSTEP) issue(step + 2, (step + 2) % 3);

        int c = step & 63;
        if (c == 0) {
#pragma unroll
            for (int j = 0; j < 16; j++)
#pragma unroll
                for (int q = 0; q < 4; q++) sacc[j][q] = 0.f;
        }
        uint32_t aB = aU + s*8192, wB = wU + s*8192;
#pragma unroll
        for (int ks = 0; ks < 2; ks++) {
            uint32_t af[4];
            {
                int row = wm + frow;
                int ch = 2*ks + fch;
                ldsm4(af, aB + row*64 + ((ch ^ ((row>>1)&3)) << 4));
            }
#pragma unroll
            for (int nn = 0; nn < 8; nn++) {
                uint32_t bf[4];
                int row = nn*16 + frow;
                int ch = 2*ks + fch;
                ldsm4(bf, wB + row*64 + ((ch ^ ((row>>1)&3)) << 4));
                mma16816(sacc[2*nn],   af, bf[0], bf[2]);
                mma16816(sacc[2*nn+1], af, bf[1], bf[3]);
            }
        }

        if (c == 63) {
            int nt = step >> 6;
            // tile row max
            float t0 = -1e30f, t1 = -1e30f;
#pragma unroll
            for (int j = 0; j < 16; j++) {
                t0 = fmaxf(t0, fmaxf(sacc[j][0], sacc[j][1]));
                t1 = fmaxf(t1, fmaxf(sacc[j][2], sacc[j][3]));
            }
            t0 = fmaxf(t0, __shfl_xor_sync(0xffffffff, t0, 1));
            t0 = fmaxf(t0, __shfl_xor_sync(0xffffffff, t0, 2));
            t1 = fmaxf(t1, __shfl_xor_sync(0xffffffff, t1, 1));
            t1 = fmaxf(t1, __shfl_xor_sync(0xffffffff, t1, 2));
            float mn0 = fmaxf(m0r, t0), mn1 = fmaxf(m1r, t1);
            float f0 = fexp(m0r - mn0), f1 = fexp(m1r - mn1);
            m0r = mn0; m1r = mn1;
            // P + partial sums
            uint32_t pa[16][2];
            float ps0 = 0.f, ps1 = 0.f;
#pragma unroll
            for (int j = 0; j < 16; j++) {
                float p0 = fexp(sacc[j][0] - mn0);
                float p1 = fexp(sacc[j][1] - mn0);
                float p2 = fexp(sacc[j][2] - mn1);
                float p3 = fexp(sacc[j][3] - mn1);
                ps0 += p0 + p1; ps1 += p2 + p3;
                pa[j][0] = packh2(p0, p1);
                pa[j][1] = packh2(p2, p3);
            }
            l0 = l0*f0 + ps0;
            l1 = l1*f1 + ps1;
#pragma unroll
            for (int on = 0; on < 8; on++) {
                oacc[on][0] *= f0; oacc[on][1] *= f0;
                oacc[on][2] *= f1; oacc[on][3] *= f1;
            }
            // P @ V
            uint32_t vB = vU + (nt & 1)*16384;
#pragma unroll
            for (int kg = 0; kg < 8; kg++) {
                uint32_t pf[4] = { pa[2*kg][0], pa[2*kg][1], pa[2*kg+1][0], pa[2*kg+1][1] };
#pragma unroll
                for (int jj = 0; jj < 4; jj++) {
                    uint32_t bt[4];
                    int krow = kg*16 + frow;
                    int ch = jj*2 + fch;
                    ldsm4t(bt, vB + krow*128 + ((ch ^ (krow&7)) << 4));
                    mma16816(oacc[2*jj],   pf, bt[0], bt[1]);
                    mma16816(oacc[2*jj+1], pf, bt[2], bt[3]);
                }
            }
        }
    }
    // finalize
    l0 += __shfl_xor_sync(0xffffffff, l0, 1);
    l0 += __shfl_xor_sync(0xffffffff, l0, 2);
    l1 += __shfl_xor_sync(0xffffffff, l1, 1);
    l1 += __shfl_xor_sync(0xffffffff, l1, 2);
    float inv0 = alpha / l0, inv1 = alpha / l1;
    const int r = lane >> 2, cq = (lane & 3)*2;
#pragma unroll
    for (int on = 0; on < 8; on++) {
        int cc = on*8 + cq;
        size_t ix0 = ((size_t)b*NN + m0 + wm + r)*DD + cc;
        size_t ix1 = ((size_t)b*NN + m0 + wm + r + 8)*DD + cc;
        atomicAdd(&out[ix0],   inv0*oacc[on][0]);
        atomicAdd(&out[ix0+1], inv0*oacc[on][1]);
        atomicAdd(&out[ix1],   inv1*oacc[on][2]);
        atomicAdd(&out[ix1+1], inv1*oacc[on][3]);
    }
}

// ---------------- launch ----------------
extern "C" void kernel_launch(void* const* d_in, const int* in_sizes, int n_in,
                              void* d_out, int out_size) {
    const float* x       = (const float*)d_in[0];
    const float* state   = (const float*)d_in[1];
    const float* E       = (const float*)d_in[2];
    const float* Wc      = (const float*)d_in[3];
    const float* Wd      = (const float*)d_in[4];
    const float* gate_w  = (const float*)d_in[5];
    const float* gate_b  = (const float*)d_in[6];
    const float* upd_w   = (const float*)d_in[7];
    const float* upd_b   = (const float*)d_in[8];
    float* out = (float*)d_out;

    const int SX_SMEM = SX_NSTG * 32768;
    cudaFuncSetAttribute(k_sx_mma, cudaFuncAttributeMaxDynamicSharedMemorySize, SX_SMEM);
    const int FL_SMEM = 6*8192 + 2*16384;   // 80KB
    cudaFuncSetAttribute(k_flash, cudaFuncAttributeMaxDynamicSharedMemorySize, FL_SMEM);

    float* d_Wg; cudaGetSymbolAddress((void**)&d_Wg, g_Wg);
    float* d_Wu; cudaGetSymbolAddress((void**)&d_Wu, g_Wu);

    // adjacency + supports + sign mask
    k_embed_outer<<<dim3(128,128), dim3(16,16)>>>(E);
    k_srowsoftmax<<<NN, 256>>>();

    // per-node weights + weight transposes
    k_mkW2<<<dim3((2*DIN*OG)/128, NN/128), 256>>>(E, gate_w, 2*DIN*OG, d_Wg);
    k_mkW2<<<dim3((2*DIN*OU)/128, NN/128), 256>>>(E, upd_w,  2*DIN*OU, d_Wu);
    k_convW<<<dim3(64,64), dim3(32,8)>>>(Wc, 0);
    k_convW<<<dim3(64,64), dim3(32,8)>>>(Wd, 1);

    // gate path
    k_concat<<<(NN*XCOLS + 255)/256, 256>>>(x, state);
    k_sx_mma<<<dim3(XPAD/128, NN/128), 256, SX_SMEM>>>(0);
    k_gate_apply<<<NN, 128>>>(E, gate_b, state);

    // update path
    k_sx_mma<<<dim3(XPAD/128, NN/128), 256, SX_SMEM>>>(1);
    k_upd_apply<<<NN, 64>>>(E, upd_b, state, out);

    // HHT -> masked fp16 (both branches)
    k_hht_mma<<<dim3(16,16,16), 256>>>();

    // fused masked-GEMM + softmax + @h, both branches
    k_flash<<<dim3(16, 32), 256, FL_SMEM>>>(out);
}

// round 10
// speedup vs baseline: 1.3028x; 1.3028x over previous
#include <cuda_runtime.h>
#include <cuda_fp16.h>
#include <cstdint>
#include <math.h>

// ---------------- problem constants ----------------
#define NN   2048
#define BB   16
#define DD   64
#define DIN  66
#define EMB  16
#define OG   128
#define OU   64
#define XCOLS (BB*DIN)   // 1056
#define XPAD  1152

// ---------------- device scratch ----------------
__device__ float g_A   [(size_t)NN*NN];
__device__ unsigned char g_mask[(size_t)NN*NN];
__device__ float g_Wg  [(size_t)NN*2*DIN*OG];
__device__ float g_Wu  [(size_t)NN*2*DIN*OU];
__device__ float g_inpT[(size_t)NN*XCOLS];
__device__ float g_candT[(size_t)NN*XCOLS];
__device__ float g_xg1T[(size_t)NN*XPAD];
__device__ float g_xg2T[(size_t)NN*XPAD];
__device__ float g_r   [(size_t)BB*NN*DD];
__device__ float g_h   [(size_t)BB*NN*DD];
__device__ __half g_h16 [(size_t)BB*NN*DD];
__device__ __half g_shi[(size_t)NN*NN];
__device__ __half g_slo[(size_t)NN*NN];
__device__ __half g_xinhi[(size_t)NN*XPAD];
__device__ __half g_xcahi[(size_t)NN*XPAD];
__device__ __half g_ac[(size_t)BB*NN*NN];
__device__ __half g_ad[(size_t)BB*NN*NN];
__device__ __half g_wc[(size_t)NN*NN];
__device__ __half g_wd[(size_t)NN*NN];
__device__ __half g_deg16[(size_t)2*BB*NN*NN];   // logits -> exp in place
__device__ float g_pmax[(size_t)2*BB*16*NN];
__device__ float g_invsum[(size_t)2*BB*NN];

// ---------------- asm helpers ----------------
__device__ __forceinline__ uint32_t s2u(const void* p) {
    return (uint32_t)__cvta_generic_to_shared(p);
}
__device__ __forceinline__ void cp16(uint32_t dst, const void* src) {
    asm volatile("cp.async.cg.shared.global [%0], [%1], 16;" :: "r"(dst), "l"(src));
}
__device__ __forceinline__ void cpcommit() { asm volatile("cp.async.commit_group;"); }
__device__ __forceinline__ void ldsm4(uint32_t* r, uint32_t addr) {
    asm volatile("ldmatrix.sync.aligned.m8n8.x4.shared.b16 {%0,%1,%2,%3}, [%4];"
        : "=r"(r[0]), "=r"(r[1]), "=r"(r[2]), "=r"(r[3]) : "r"(addr));
}
__device__ __forceinline__ void ldsm4t(uint32_t* r, uint32_t addr) {
    asm volatile("ldmatrix.sync.aligned.m8n8.x4.trans.shared.b16 {%0,%1,%2,%3}, [%4];"
        : "=r"(r[0]), "=r"(r[1]), "=r"(r[2]), "=r"(r[3]) : "r"(addr));
}
__device__ __forceinline__ void mma16816(float* c, const uint32_t* a, uint32_t b0, uint32_t b1) {
    asm volatile(
        "mma.sync.aligned.m16n8k16.row.col.f32.f16.f16.f32 "
        "{%0,%1,%2,%3}, {%4,%5,%6,%7}, {%8,%9}, {%0,%1,%2,%3};"
        : "+f"(c[0]), "+f"(c[1]), "+f"(c[2]), "+f"(c[3])
        : "r"(a[0]), "r"(a[1]), "r"(a[2]), "r"(a[3]), "r"(b0), "r"(b1));
}
__device__ __forceinline__ float fexp(float x) {
    float t = fmaxf(x * 1.4426950408889634f, -125.f);
    int   ni = __float2int_rn(t);
    float f  = t - (float)ni;
    float p = 0.00133335581f;
    p = fmaf(p, f, 0.00961812910f);
    p = fmaf(p, f, 0.05550410866f);
    p = fmaf(p, f, 0.24022650696f);
    p = fmaf(p, f, 0.69314718056f);
    p = fmaf(p, f, 1.0f);
    return p * __int_as_float((ni + 127) << 23);
}

// ---------------- A = E E^T + sign mask ----------------
__global__ void k_embed_outer(const float* __restrict__ E) {
    __shared__ float En[16][17], Em[16][17];
    int tx = threadIdx.x, ty = threadIdx.y;
    En[ty][tx] = E[((size_t)blockIdx.y*16 + ty)*EMB + tx];
    Em[ty][tx] = E[((size_t)blockIdx.x*16 + ty)*EMB + tx];
    __syncthreads();
    float s = 0.f;
#pragma unroll
    for (int e = 0; e < 16; e++) s += En[ty][e] * Em[tx][e];
    size_t idx = ((size_t)blockIdx.y*16 + ty)*NN + blockIdx.x*16 + tx;
    g_A[idx] = s;
    g_mask[idx] = (s > 0.f) ? 1 : ((s < 0.f) ? 2 : 0);
}

// ---------------- S softmax: relu(A) -> fp16 hi/lo ----------------
__global__ void k_srowsoftmax() {
    __shared__ float buf[NN];
    __shared__ float red[256];
    int row = blockIdx.x;
    int tid = threadIdx.x;
    const float* in = g_A + (size_t)row*NN;
    float mx = -1e30f;
    for (int i = tid; i < NN; i += 256) {
        float v = in[i];
        v = v > 0.f ? v : 0.f;
        buf[i] = v;
        mx = fmaxf(mx, v);
    }
    red[tid] = mx; __syncthreads();
    for (int s = 128; s > 0; s >>= 1) {
        if (tid < s) red[tid] = fmaxf(red[tid], red[tid+s]);
        __syncthreads();
    }
    mx = red[0];
    __syncthreads();
    float sum = 0.f;
    for (int i = tid; i < NN; i += 256) {
        float e = fexp(buf[i] - mx);
        buf[i] = e;
        sum += e;
    }
    red[tid] = sum; __syncthreads();
    for (int s = 128; s > 0; s >>= 1) {
        if (tid < s) red[tid] += red[tid+s];
        __syncthreads();
    }
    float inv = 1.0f / red[0];
    for (int i = tid; i < NN; i += 256) {
        float v = buf[i] * inv;
        __half hi = __float2half_rn(v);
        g_shi[(size_t)row*NN + i] = hi;
        g_slo[(size_t)row*NN + i] = __float2half_rn(v - __half2float(hi));
    }
}

// ---------------- exp + rowsum (in place), both branches ----------------
__global__ void __launch_bounds__(256) k_expsum() {
    int row = blockIdx.x, b2 = blockIdx.y, tid = threadIdx.x;
    int b = b2 & 15, br = b2 >> 4;
    __half2* io = (__half2*)(g_deg16 + (((size_t)br*BB + b)*NN + row)*NN);
    __shared__ float red[256];
    float mx = -1e30f;
#pragma unroll
    for (int nt = 0; nt < 16; nt++)
        mx = fmaxf(mx, g_pmax[(((size_t)br*BB + b)*16 + nt)*NN + row]);
    float2 e[4];
    float sum = 0.f;
#pragma unroll
    for (int t = 0; t < 4; t++) {
        float2 f = __half22float2(io[tid + t*256]);
        e[t].x = fexp(f.x - mx);
        e[t].y = fexp(f.y - mx);
        sum += e[t].x + e[t].y;
    }
    red[tid] = sum; __syncthreads();
    for (int s = 128; s > 0; s >>= 1) {
        if (tid < s) red[tid] += red[tid+s];
        __syncthreads();
    }
    if (tid == 0) g_invsum[((size_t)br*BB + b)*NN + row] = 1.0f / red[0];
#pragma unroll
    for (int t = 0; t < 4; t++)
        io[tid + t*256] = __floats2half2_rn(e[t].x, e[t].y);
}

// ---------------- per-node weights, tiled ----------------
__global__ void __launch_bounds__(256) k_mkW2(const float* __restrict__ E,
                                              const float* __restrict__ pool,
                                              int per_e, float* __restrict__ W) {
    __shared__ __align__(16) float Es[16][128];
    __shared__ __align__(16) float Ps[16][128];
    int tid = threadIdx.x;
    int j0 = blockIdx.x*128, m0 = blockIdx.y*128;
    {
        int r = tid >> 1, e0 = (tid & 1)*8;
        float4 a = *(const float4*)&E[(size_t)(m0+r)*EMB + e0];
        float4 b = *(const float4*)&E[(size_t)(m0+r)*EMB + e0 + 4];
        Es[e0+0][r]=a.x; Es[e0+1][r]=a.y; Es[e0+2][r]=a.z; Es[e0+3][r]=a.w;
        Es[e0+4][r]=b.x; Es[e0+5][r]=b.y; Es[e0+6][r]=b.z; Es[e0+7][r]=b.w;
    }
    {
        int e = tid >> 4, c0 = (tid & 15)*8;
        float4 a = *(const float4*)&pool[(size_t)e*per_e + j0 + c0];
        float4 b = *(const float4*)&pool[(size_t)e*per_e + j0 + c0 + 4];
        *(float4*)&Ps[e][c0]   = a;
        *(float4*)&Ps[e][c0+4] = b;
    }
    __syncthreads();
    int row0 = (tid/16)*8, col0 = (tid%16)*8;
    float acc[8][8] = {};
#pragma unroll
    for (int k = 0; k < 16; k++) {
        float av[8], bv[8];
        float4 t;
        t = *(const float4*)&Es[k][row0];   av[0]=t.x; av[1]=t.y; av[2]=t.z; av[3]=t.w;
        t = *(const float4*)&Es[k][row0+4]; av[4]=t.x; av[5]=t.y; av[6]=t.z; av[7]=t.w;
        t = *(const float4*)&Ps[k][col0];   bv[0]=t.x; bv[1]=t.y; bv[2]=t.z; bv[3]=t.w;
        t = *(const float4*)&Ps[k][col0+4]; bv[4]=t.x; bv[5]=t.y; bv[6]=t.z; bv[7]=t.w;
#pragma unroll
        for (int i = 0; i < 8; i++)
#pragma unroll
            for (int j = 0; j < 8; j++) acc[i][j] += av[i]*bv[j];
    }
#pragma unroll
    for (int i = 0; i < 8; i++) {
        size_t ro = (size_t)(m0 + row0 + i)*per_e + j0 + col0;
        *(float4*)&W[ro]   = make_float4(acc[i][0], acc[i][1], acc[i][2], acc[i][3]);
        *(float4*)&W[ro+4] = make_float4(acc[i][4], acc[i][5], acc[i][6], acc[i][7]);
    }
}

// ---------------- concat (X stored fp32 + fp16 hi only) ----------------
__global__ void k_concat(const float* __restrict__ x, const float* __restrict__ state) {
    int idx = blockIdx.x*256 + threadIdx.x;
    if (idx >= NN*XCOLS) return;
    int n = idx / XCOLS;
    int rem = idx % XCOLS;
    int b = rem / DIN, i = rem % DIN;
    float v;
    if (i < 2) v = x[((size_t)b*NN + n)*2 + i];
    else       v = state[((size_t)b*NN + n)*DD + (i-2)];
    g_inpT[idx] = v;
    __half hi = __float2half_rn(v);
    size_t pidx = (size_t)n*XPAD + rem;
    g_xinhi[pidx] = hi;
    if (i < 2) {
        g_candT[idx] = v;
        g_xcahi[pidx] = hi;
    }
}

// ---------------- xg = S @ X on HMMA (2 passes: Shi*X + Slo*X) ----------------
#define SX_NSTG 3
#define SX_STAGE 24576
__global__ void __launch_bounds__(256, 2) k_sx_mma(int which) {
    extern __shared__ __align__(16) __half dsm[];
    const __half* Bhi = which ? g_xcahi : g_xinhi;
    float* C = which ? g_xg2T : g_xg1T;

    const int tid = threadIdx.x;
    const int n0 = blockIdx.x*128;
    const int m0 = blockIdx.y*128;
    uint32_t su = s2u(dsm);

    const int rowA = tid >> 1, ap0 = (tid & 1)*2;
    const int rowB = tid >> 3, bp0 = (tid & 7)*2;
    const size_t aRow = (size_t)(m0 + rowA)*NN;
    uint32_t dA[2], dB[2];
#pragma unroll
    for (int t = 0; t < 2; t++) {
        int ch = ap0 + t;
        dA[t] = rowA*64 + ((ch ^ ((rowA>>1)&3)) << 4);
        int cb = bp0 + t;
        dB[t] = 16384 + rowB*256 + ((cb ^ (rowB&7)) << 4);
    }

    auto issue = [&](int c, int s) {
        uint32_t base = su + s*SX_STAGE;   // stage: Shi 0 | Slo 8192 | X 16384
#pragma unroll
        for (int t = 0; t < 2; t++) {
            int ch = ap0 + t;
            cp16(base + dA[t],        g_shi + aRow + c*32 + ch*8);
            cp16(base + 8192 + dA[t], g_slo + aRow + c*32 + ch*8);
        }
#pragma unroll
        for (int t = 0; t < 2; t++) {
            int cb = bp0 + t;
            size_t bo = (size_t)(c*32 + rowB)*XPAD + n0 + cb*8;
            cp16(base + dB[t], Bhi + bo);
        }
        cpcommit();
    };

    const int lane = tid & 31, wid = tid >> 5;
    const int wm = (wid & 1)*64, wn = (wid >> 1)*32;
    const int frow = ((lane>>3)&1)*8 + (lane&7);
    const int fch  = lane >> 4;

    float acc[4][4][4] = {};
    issue(0, 0); issue(1, 1);
    const int NC = NN/32;
    for (int c = 0; c < NC; c++) {
        int s = c % SX_NSTG;
        if (c + 1 < NC) asm volatile("cp.async.wait_group 1;" ::: "memory");
        else            asm volatile("cp.async.wait_group 0;" ::: "memory");
        __syncthreads();
        if (c + 2 < NC) issue(c + 2, (c + 2) % SX_NSTG);
        uint32_t base = su + s*SX_STAGE;
#pragma unroll
        for (int ks = 0; ks < 2; ks++) {
            uint32_t af[4][4], bh[2][4];
#pragma unroll
            for (int i = 0; i < 4; i++) {
                int row = wm + i*16 + frow;
                int ch = 2*ks + fch;
                ldsm4(af[i], base + row*64 + ((ch ^ ((row>>1)&3)) << 4));
            }
#pragma unroll
            for (int jj = 0; jj < 2; jj++) {
                int krow = ks*16 + frow;
                int ch = (wn >> 3) + jj*2 + fch;
                ldsm4t(bh[jj], base + 16384 + krow*256 + ((ch ^ (krow&7)) << 4));
            }
#pragma unroll
            for (int i = 0; i < 4; i++)
#pragma unroll
                for (int j = 0; j < 4; j++) {
                    int jj = j >> 1, sb = (j & 1)*2;
                    mma16816(acc[i][j], af[i], bh[jj][sb], bh[jj][sb+1]);
                }
            // lo pass (S correction)
#pragma unroll
            for (int i = 0; i < 4; i++) {
                int row = wm + i*16 + frow;
                int ch = 2*ks + fch;
                ldsm4(af[i], base + 8192 + row*64 + ((ch ^ ((row>>1)&3)) << 4));
            }
#pragma unroll
            for (int i = 0; i < 4; i++)
#pragma unroll
                for (int j = 0; j < 4; j++) {
                    int jj = j >> 1, sb = (j & 1)*2;
                    mma16816(acc[i][j], af[i], bh[jj][sb], bh[jj][sb+1]);
                }
        }
    }
    const int r = lane >> 2, cq = (lane & 3)*2;
#pragma unroll
    for (int i = 0; i < 4; i++) {
        int r0 = m0 + wm + i*16 + r;
#pragma unroll
        for (int j = 0; j < 4; j++) {
            int cc = n0 + wn + j*8 + cq;
            *(float2*)&C[(size_t)r0*XPAD + cc]     = make_float2(acc[i][j][0], acc[i][j][1]);
            *(float2*)&C[(size_t)(r0+8)*XPAD + cc] = make_float2(acc[i][j][2], acc[i][j][3]);
        }
    }
}

// ---------------- gate apply ----------------
__global__ void k_gate_apply(const float* __restrict__ E, const float* __restrict__ gate_b,
                             const float* __restrict__ state) {
    int n = blockIdx.x;
    int o = threadIdx.x;
    __shared__ float Xs[BB][2*DIN];
    __shared__ float Es[16];
    if (o < 16) Es[o] = E[(size_t)n*EMB + o];
    for (int idx = o; idx < BB*2*DIN; idx += 128) {
        int bb = idx / (2*DIN), i = idx % (2*DIN);
        float v = (i < DIN) ? g_inpT[(size_t)n*XCOLS + bb*DIN + i]
                            : g_xg1T[(size_t)n*XPAD + bb*DIN + (i - DIN)];
        Xs[bb][i] = v;
    }
    __syncthreads();
    float bias = 0.f;
#pragma unroll
    for (int e = 0; e < 16; e++) bias += Es[e] * gate_b[e*OG + o];
    float acc[BB];
#pragma unroll
    for (int bb = 0; bb < BB; bb++) acc[bb] = bias;
    const float* Wn = g_Wg + (size_t)n*(2*DIN*OG);
    for (int i = 0; i < 2*DIN; i++) {
        float w = Wn[(size_t)i*OG + o];
#pragma unroll
        for (int bb = 0; bb < BB; bb++) acc[bb] += Xs[bb][i] * w;
    }
#pragma unroll
    for (int bb = 0; bb < BB; bb++) {
        float v = 1.0f / (1.0f + __expf(-acc[bb]));
        if (o < DD) {
            float st = state[((size_t)bb*NN + n)*DD + o];
            float zs = v * st;
            g_candT[(size_t)n*XCOLS + bb*DIN + 2 + o] = zs;
            g_xcahi[(size_t)n*XPAD + bb*DIN + 2 + o] = __float2half_rn(zs);
        } else {
            g_r[((size_t)bb*NN + n)*DD + (o - DD)] = v;
        }
    }
}

// ---------------- update apply: h, h16, out base 0.8h ----------------
__global__ void k_upd_apply(const float* __restrict__ E, const float* __restrict__ upd_b,
                            const float* __restrict__ state, float* __restrict__ out) {
    int n = blockIdx.x;
    int o = threadIdx.x;
    __shared__ float Xs[BB][2*DIN];
    __shared__ float Es[16];
    if (o < 16) Es[o] = E[(size_t)n*EMB + o];
    for (int idx = o; idx < BB*2*DIN; idx += 64) {
        int bb = idx / (2*DIN), i = idx % (2*DIN);
        Xs[bb][i] = (i < DIN) ? g_candT[(size_t)n*XCOLS + bb*DIN + i]
                              : g_xg2T[(size_t)n*XPAD + bb*DIN + (i - DIN)];
    }
    __syncthreads();
    float bias = 0.f;
#pragma unroll
    for (int e = 0; e < 16; e++) bias += Es[e] * upd_b[e*OU + o];
    float acc[BB];
#pragma unroll
    for (int bb = 0; bb < BB; bb++) acc[bb] = bias;
    const float* Wn = g_Wu + (size_t)n*(2*DIN*OU);
    for (int i = 0; i < 2*DIN; i++) {
        float w = Wn[(size_t)i*OU + o];
#pragma unroll
        for (int bb = 0; bb < BB; bb++) acc[bb] += Xs[bb][i] * w;
    }
#pragma unroll
    for (int bb = 0; bb < BB; bb++) {
        float hc = tanhf(acc[bb]);
        size_t ix = ((size_t)bb*NN + n)*DD + o;
        float r = g_r[ix];
        float hv = r * state[ix] + (1.0f - r) * hc;
        g_h[ix] = hv;
        g_h16[ix] = __float2half_rn(hv);
        out[ix] = 0.8f * hv;
    }
}

// ---------------- HHT on HMMA: g_ac/g_ad = mask(.) * (h16 @ h16^T) ----------------
__global__ void __launch_bounds__(256, 2) k_hht_mma() {
    __shared__ __align__(16) __half sA[128*64];
    __shared__ __align__(16) __half sB[128*64];
    const int tid = threadIdx.x;
    const int b = blockIdx.z, m0 = blockIdx.y*128, n0 = blockIdx.x*128;
    uint32_t aU = s2u(sA), bU = s2u(sB);

    const int row = tid >> 1, c0 = (tid & 1)*4;
#pragma unroll
    for (int t = 0; t < 4; t++) {
        int ch = c0 + t;
        uint32_t off = row*128 + ((ch ^ (row&7)) << 4);
        cp16(aU + off, g_h16 + ((size_t)b*NN + m0 + row)*64 + ch*8);
        cp16(bU + off, g_h16 + ((size_t)b*NN + n0 + row)*64 + ch*8);
    }
    cpcommit();
    asm volatile("cp.async.wait_group 0;" ::: "memory");
    __syncthreads();

    const int lane = tid & 31, wid = tid >> 5;
    const int wm = (wid & 1)*64, wn = (wid >> 1)*32;
    const int frow = ((lane>>3)&1)*8 + (lane&7);
    const int fch  = lane >> 4;

    float acc[4][4][4] = {};
#pragma unroll
    for (int ks = 0; ks < 4; ks++) {
        uint32_t af[4][4], bf[2][4];
#pragma unroll
        for (int i = 0; i < 4; i++) {
            int rr = wm + i*16 + frow;
            int ch = 2*ks + fch;
            ldsm4(af[i], aU + rr*128 + ((ch ^ (rr&7)) << 4));
        }
#pragma unroll
        for (int jj = 0; jj < 2; jj++) {
            int rr = wn + jj*16 + frow;
            int ch = 2*ks + fch;
            ldsm4(bf[jj], bU + rr*128 + ((ch ^ (rr&7)) << 4));
        }
#pragma unroll
        for (int i = 0; i < 4; i++)
#pragma unroll
            for (int j = 0; j < 4; j++) {
                int jj = j >> 1, sb = j & 1;
                mma16816(acc[i][j], af[i], bf[jj][sb], bf[jj][sb+2]);
            }
    }
    const int r = lane >> 2, cq = (lane & 3)*2;
#pragma unroll
    for (int i = 0; i < 4; i++) {
        int rbase = m0 + wm + i*16 + r;
#pragma unroll
        for (int j = 0; j < 4; j++) {
            int cc = n0 + wn + j*8 + cq;
#pragma unroll
            for (int hh = 0; hh < 2; hh++) {
                int rr = rbase + hh*8;
                uchar2 mk = *(const uchar2*)&g_mask[(size_t)rr*NN + cc];
                float v0 = acc[i][j][hh*2+0], v1 = acc[i][j][hh*2+1];
                __half2 hc = __floats2half2_rn(mk.x == 1 ? v0 : 0.f, mk.y == 1 ? v1 : 0.f);
                __half2 hd = __floats2half2_rn(mk.x == 2 ? v0 : 0.f, mk.y == 2 ? v1 : 0.f);
                *(__half2*)&g_ac[((size_t)b*NN + rr)*NN + cc] = hc;
                *(__half2*)&g_ad[((size_t)b*NN + rr)*NN + cc] = hd;
            }
        }
    }
}

// ---------------- W (fp32 [k][n]) -> transposed fp16 Wt[n][k], both in one launch ----------------
__global__ void k_convW(const float* __restrict__ Wc, const float* __restrict__ Wd) {
    __shared__ float t[32][33];
    int tx = threadIdx.x, ty = threadIdx.y;
    int bx = blockIdx.x*32, by = blockIdx.y*32;
    const float* W = blockIdx.z ? Wd : Wc;
    __half* Wt = blockIdx.z ? g_wd : g_wc;
    for (int j = 0; j < 32; j += 8)
        t[ty+j][tx] = W[(size_t)(by+ty+j)*NN + bx+tx];
    __syncthreads();
    for (int j = 0; j < 32; j += 8) {
        float v = t[tx][ty+j];
        Wt[(size_t)(bx+ty+j)*NN + by+tx] = __float2half_rn(v);
    }
}

// ---------------- big GEMM: both branches, 256x128 CTA, 8 warps, warp tile 64x64 ----------------
#define BG_NSTG 3
__global__ void __launch_bounds__(256, 1) k_biggemm_mma() {
    __shared__ __align__(16) __half sA[BG_NSTG][256*32];
    __shared__ __align__(16) __half sW[BG_NSTG][128*32];
    __shared__ float smax[2][256];
    const int tid = threadIdx.x;
    const int bz = blockIdx.z, b = bz & 15, br = bz >> 4;
    const int m0 = blockIdx.y*256, n0 = blockIdx.x*128;
    const __half* Am = ((br == 0) ? g_ac : g_ad) + (size_t)b*NN*NN;
    const __half* Wt = (br == 0) ? g_wc : g_wd;
    uint32_t aU = s2u(sA), wU = s2u(sW);

    const int rowA = tid >> 1, ap0 = (tid & 1)*2;
    const int rowW = tid >> 2, chW = tid & 3;
    const size_t aRow0 = (size_t)(m0 + rowA)*NN;
    const size_t aRow1 = (size_t)(m0 + rowA + 128)*NN;
    const size_t wRow0 = (size_t)(n0 + rowW)*NN;
    const size_t wRow1 = (size_t)(n0 + rowW + 64)*NN;
    uint32_t dA[2];
#pragma unroll
    for (int t = 0; t < 2; t++) {
        int ch = ap0 + t;
        dA[t] = rowA*64 + ((ch ^ ((rowA>>1)&3)) << 4);
    }
    const uint32_t dW = rowW*64 + ((chW ^ ((rowW>>1)&3)) << 4);

    auto issue = [&](int c, int s) {
#pragma unroll
        for (int t = 0; t < 2; t++) {
            cp16(aU + s*16384 + dA[t],            Am + aRow0 + c*32 + (ap0+t)*8);
            cp16(aU + s*16384 + dA[t] + 128*64,   Am + aRow1 + c*32 + (ap0+t)*8);
        }
        cp16(wU + s*8192 + dW,           Wt + wRow0 + c*32 + chW*8);
        cp16(wU + s*8192 + dW + 64*64,   Wt + wRow1 + c*32 + chW*8);
        cpcommit();
    };

    const int lane = tid & 31, wid = tid >> 5;
    const int wm = (wid & 3)*64;
    const int wn = (wid >> 2)*64;
    const int frow = ((lane>>3)&1)*8 + (lane&7);
    const int fch  = lane >> 4;

    float acc[4][8][4] = {};
    issue(0, 0); issue(1, 1);
    const int NC = NN/32;
    for (int c = 0; c < NC; c++) {
        int s = c % BG_NSTG;
        if (c + 1 < NC) asm volatile("cp.async.wait_group 1;" ::: "memory");
        else            asm volatile("cp.async.wait_group 0;" ::: "memory");
        __syncthreads();
        if (c + 2 < NC) issue(c + 2, (c + 2) % BG_NSTG);
        uint32_t aB = aU + s*16384, wB = wU + s*8192;
#pragma unroll
        for (int ks = 0; ks < 2; ks++) {
            uint32_t af[4][4], bf[4][4];
#pragma unroll
            for (int i = 0; i < 4; i++) {
                int row = wm + i*16 + frow;
                int ch = 2*ks + fch;
                ldsm4(af[i], aB + row*64 + ((ch ^ ((row>>1)&3)) << 4));
            }
#pragma unroll
            for (int jj = 0; jj < 4; jj++) {
                int row = wn + jj*16 + frow;
                int ch = 2*ks + fch;
                ldsm4(bf[jj], wB + row*64 + ((ch ^ ((row>>1)&3)) << 4));
            }
#pragma unroll
            for (int i = 0; i < 4; i++)
#pragma unroll
                for (int j = 0; j < 8; j++) {
                    int jj = j >> 1, sb = j & 1;
                    mma16816(acc[i][j], af[i], bf[jj][sb], bf[jj][sb+2]);
                }
        }
    }
    __half* C = g_deg16 + (((size_t)br*BB + b)*NN)*NN;
    const int r = lane >> 2, cq = (lane & 3)*2;
#pragma unroll
    for (int i = 0; i < 4; i++) {
#pragma unroll
        for (int hh = 0; hh < 2; hh++) {
            int r0 = m0 + wm + i*16 + hh*8 + r;
            float m = -1e30f;
#pragma unroll
            for (int j = 0; j < 8; j++) {
                float v0 = acc[i][j][hh*2+0], v1 = acc[i][j][hh*2+1];
                m = fmaxf(m, fmaxf(v0, v1));
                int cc = n0 + wn + j*8 + cq;
                *(__half2*)&C[(size_t)r0*NN + cc] = __floats2half2_rn(v0, v1);
            }
            m = fmaxf(m, __shfl_xor_sync(0xffffffff, m, 1));
            m = fmaxf(m, __shfl_xor_sync(0xffffffff, m, 2));
            if ((lane & 3) == 0) smax[wid >> 2][wm + i*16 + hh*8 + r] = m;
        }
    }
    __syncthreads();
    if (tid < 256) {
        float m2 = fmaxf(smax[0][tid], smax[1][tid]);
        g_pmax[(((size_t)br*BB + b)*16 + blockIdx.x)*NN + m0 + tid] = m2;
    }
}

// ---------------- deg @ h on HMMA, both branches, atomicAdd into out ----------------
#define DH_NSTG 3
__global__ void __launch_bounds__(256, 2) k_deg_h_mma(float* __restrict__ out) {
    __shared__ __align__(16) __half sA[DH_NSTG][128*32];
    __shared__ __align__(16) __half sB[DH_NSTG][32*64];
    const int tid = threadIdx.x;
    const int bz = blockIdx.z, b = bz & 15, br = bz >> 4;
    const int m0 = blockIdx.y*128;
    const float alpha = (br == 0) ? -0.1f : 0.1f;
    const __half* Ap = g_deg16 + (((size_t)br*BB + b)*NN)*NN;
    const __half* Hp = g_h16 + (size_t)b*NN*DD;
    const float* inv = g_invsum + ((size_t)br*BB + b)*NN;
    uint32_t aU = s2u(sA), bU = s2u(sB);

    const int rowA = tid >> 1, ap0 = (tid & 1)*2;
    const size_t aRow = (size_t)(m0 + rowA)*NN;
    const int rowB = tid >> 3, chB = tid & 7;
    const uint32_t dB = rowB*128 + ((chB ^ (rowB&7)) << 4);

    auto issue = [&](int c, int s) {
#pragma unroll
        for (int t = 0; t < 2; t++) {
            int ch = ap0 + t;
            cp16(aU + s*8192 + rowA*64 + ((ch ^ ((rowA>>1)&3)) << 4),
                 Ap + aRow + c*32 + ch*8);
        }
        cp16(bU + s*4096 + dB, Hp + (size_t)(c*32 + rowB)*DD + chB*8);
        cpcommit();
    };

    const int lane = tid & 31, wid = tid >> 5;
    const int wm = (wid & 3)*32;
    const int wn = (wid >> 2)*32;
    const int frow = ((lane>>3)&1)*8 + (lane&7);
    const int fch  = lane >> 4;

    float acc[2][4][4] = {};
    issue(0, 0); issue(1, 1);
    const int NC = NN/32;
    for (int c = 0; c < NC; c++) {
        int s = c % DH_NSTG;
        if (c + 1 < NC) asm volatile("cp.async.wait_group 1;" ::: "memory");
        else            asm volatile("cp.async.wait_group 0;" ::: "memory");
        __syncthreads();
        if (c + 2 < NC) issue(c + 2, (c + 2) % DH_NSTG);
        uint32_t aB = aU + s*8192, bBs = bU + s*4096;
#pragma unroll
        for (int ks = 0; ks < 2; ks++) {
            uint32_t af[2][4], bt[2][4];
#pragma unroll
            for (int i = 0; i < 2; i++) {
                int row = wm + i*16 + frow;
                int ch = 2*ks + fch;
                ldsm4(af[i], aB + row*64 + ((ch ^ ((row>>1)&3)) << 4));
            }
#pragma unroll
            for (int jj = 0; jj < 2; jj++) {
                int krow = ks*16 + frow;
                int ch = (wn >> 3) + jj*2 + fch;
                ldsm4t(bt[jj], bBs + krow*128 + ((ch ^ (krow&7)) << 4));
            }
#pragma unroll
            for (int i = 0; i < 2; i++)
#pragma unroll
                for (int j = 0; j < 4; j++) {
                    int jj = j >> 1, sb = (j & 1)*2;
                    mma16816(acc[i][j], af[i], bt[jj][sb], bt[jj][sb+1]);
                }
        }
    }
    const int r = lane >> 2, cq = (lane & 3)*2;
#pragma unroll
    for (int i = 0; i < 2; i++) {
#pragma unroll
        for (int hh = 0; hh < 2; hh++) {
            int r0 = m0 + wm + i*16 + hh*8 + r;
            float sc = alpha * inv[r0];
#pragma unroll
            for (int j = 0; j < 4; j++) {
                int cc = wn + j*8 + cq;
                size_t ix = ((size_t)b*NN + r0)*DD + cc;
                atomicAdd(&out[ix],   sc * acc[i][j][hh*2+0]);
                atomicAdd(&out[ix+1], sc * acc[i][j][hh*2+1]);
            }
        }
    }
}

// ---------------- launch ----------------
extern "C" void kernel_launch(void* const* d_in, const int* in_sizes, int n_in,
                              void* d_out, int out_size) {
    const float* x       = (const float*)d_in[0];
    const float* state   = (const float*)d_in[1];
    const float* E       = (const float*)d_in[2];
    const float* Wc      = (const float*)d_in[3];
    const float* Wd      = (const float*)d_in[4];
    const float* gate_w  = (const float*)d_in[5];
    const float* gate_b  = (const float*)d_in[6];
    const float* upd_w   = (const float*)d_in[7];
    const float* upd_b   = (const float*)d_in[8];
    float* out = (float*)d_out;

    const int SX_SMEM = SX_NSTG * SX_STAGE;   // 72KB
    cudaFuncSetAttribute(k_sx_mma, cudaFuncAttributeMaxDynamicSharedMemorySize, SX_SMEM);

    float* d_Wg; cudaGetSymbolAddress((void**)&d_Wg, g_Wg);
    float* d_Wu; cudaGetSymbolAddress((void**)&d_Wu, g_Wu);

    // adjacency + supports + sign mask
    k_embed_outer<<<dim3(128,128), dim3(16,16)>>>(E);
    k_srowsoftmax<<<NN, 256>>>();

    // per-node weights + weight transposes
    k_mkW2<<<dim3((2*DIN*OG)/128, NN/128), 256>>>(E, gate_w, 2*DIN*OG, d_Wg);
    k_mkW2<<<dim3((2*DIN*OU)/128, NN/128), 256>>>(E, upd_w,  2*DIN*OU, d_Wu);
    k_convW<<<dim3(64,64,2), dim3(32,8)>>>(Wc, Wd);

    // gate path
    k_concat<<<(NN*XCOLS + 255)/256, 256>>>(x, state);
    k_sx_mma<<<dim3(XPAD/128, NN/128), 256, SX_SMEM>>>(0);
    k_gate_apply<<<NN, 128>>>(E, gate_b, state);

    // update path
    k_sx_mma<<<dim3(XPAD/128, NN/128), 256, SX_SMEM>>>(1);
    k_upd_apply<<<NN, 64>>>(E, upd_b, state, out);

    // HHT -> masked fp16 (both branches)
    k_hht_mma<<<dim3(16,16,16), 256>>>();

    // both-branch big GEMM + softmax
    k_biggemm_mma<<<dim3(16, 8, 32), 256>>>();
    k_expsum<<<dim3(NN, 2*BB), 256>>>();

    // output: both branches, atomicAdd onto pre-written 0.8h base
    k_deg_h_mma<<<dim3(1, 16, 32), 256>>>(out);
}

// round 11
// speedup vs baseline: 1.3722x; 1.0533x over previous
#include <cuda_runtime.h>
#include <cuda_fp16.h>
#include <cstdint>
#include <math.h>

// ---------------- problem constants ----------------
#define NN   2048
#define BB   16
#define DD   64
#define DIN  66
#define EMB  16
#define OG   128
#define OU   64
#define XCOLS (BB*DIN)   // 1056
#define XPAD  1152

// ---------------- device scratch ----------------
__device__ float g_A   [(size_t)NN*NN];
__device__ unsigned char g_mask[(size_t)NN*NN];
__device__ float g_Wg  [(size_t)NN*2*DIN*OG];
__device__ float g_Wu  [(size_t)NN*2*DIN*OU];
__device__ float g_inpT[(size_t)NN*XCOLS];
__device__ float g_candT[(size_t)NN*XCOLS];
__device__ float g_xg1T[(size_t)NN*XPAD];
__device__ float g_xg2T[(size_t)NN*XPAD];
__device__ float g_r   [(size_t)BB*NN*DD];
__device__ float g_h   [(size_t)BB*NN*DD];
__device__ __half g_h16 [(size_t)BB*NN*DD];
__device__ __half g_shi[(size_t)NN*NN];
__device__ __half g_xinhi[(size_t)NN*XPAD];
__device__ __half g_xcahi[(size_t)NN*XPAD];
__device__ __half g_ac[(size_t)BB*NN*NN];
__device__ __half g_ad[(size_t)BB*NN*NN];
__device__ __half g_wc[(size_t)NN*NN];
__device__ __half g_wd[(size_t)NN*NN];
__device__ __half g_deg16[(size_t)2*BB*NN*NN];   // raw fp16 logits
__device__ float g_pmax[(size_t)2*BB*16*NN];

// ---------------- asm helpers ----------------
__device__ __forceinline__ uint32_t s2u(const void* p) {
    return (uint32_t)__cvta_generic_to_shared(p);
}
__device__ __forceinline__ void cp16(uint32_t dst, const void* src) {
    asm volatile("cp.async.cg.shared.global [%0], [%1], 16;" :: "r"(dst), "l"(src));
}
__device__ __forceinline__ void cpcommit() { asm volatile("cp.async.commit_group;"); }
__device__ __forceinline__ void ldsm4(uint32_t* r, uint32_t addr) {
    asm volatile("ldmatrix.sync.aligned.m8n8.x4.shared.b16 {%0,%1,%2,%3}, [%4];"
        : "=r"(r[0]), "=r"(r[1]), "=r"(r[2]), "=r"(r[3]) : "r"(addr));
}
__device__ __forceinline__ void ldsm4t(uint32_t* r, uint32_t addr) {
    asm volatile("ldmatrix.sync.aligned.m8n8.x4.trans.shared.b16 {%0,%1,%2,%3}, [%4];"
        : "=r"(r[0]), "=r"(r[1]), "=r"(r[2]), "=r"(r[3]) : "r"(addr));
}
__device__ __forceinline__ void mma16816(float* c, const uint32_t* a, uint32_t b0, uint32_t b1) {
    asm volatile(
        "mma.sync.aligned.m16n8k16.row.col.f32.f16.f16.f32 "
        "{%0,%1,%2,%3}, {%4,%5,%6,%7}, {%8,%9}, {%0,%1,%2,%3};"
        : "+f"(c[0]), "+f"(c[1]), "+f"(c[2]), "+f"(c[3])
        : "r"(a[0]), "r"(a[1]), "r"(a[2]), "r"(a[3]), "r"(b0), "r"(b1));
}
__device__ __forceinline__ float fexp(float x) {
    float t = fmaxf(x * 1.4426950408889634f, -125.f);
    int   ni = __float2int_rn(t);
    float f  = t - (float)ni;
    float p = 0.00133335581f;
    p = fmaf(p, f, 0.00961812910f);
    p = fmaf(p, f, 0.05550410866f);
    p = fmaf(p, f, 0.24022650696f);
    p = fmaf(p, f, 0.69314718056f);
    p = fmaf(p, f, 1.0f);
    return p * __int_as_float((ni + 127) << 23);
}

// ---------------- A = E E^T + sign mask ----------------
__global__ void k_embed_outer(const float* __restrict__ E) {
    __shared__ float En[16][17], Em[16][17];
    int tx = threadIdx.x, ty = threadIdx.y;
    En[ty][tx] = E[((size_t)blockIdx.y*16 + ty)*EMB + tx];
    Em[ty][tx] = E[((size_t)blockIdx.x*16 + ty)*EMB + tx];
    __syncthreads();
    float s = 0.f;
#pragma unroll
    for (int e = 0; e < 16; e++) s += En[ty][e] * Em[tx][e];
    size_t idx = ((size_t)blockIdx.y*16 + ty)*NN + blockIdx.x*16 + tx;
    g_A[idx] = s;
    g_mask[idx] = (s > 0.f) ? 1 : ((s < 0.f) ? 2 : 0);
}

// ---------------- S softmax: relu(A) -> fp16 ----------------
__global__ void k_srowsoftmax() {
    __shared__ float buf[NN];
    __shared__ float red[256];
    int row = blockIdx.x;
    int tid = threadIdx.x;
    const float* in = g_A + (size_t)row*NN;
    float mx = -1e30f;
    for (int i = tid; i < NN; i += 256) {
        float v = in[i];
        v = v > 0.f ? v : 0.f;
        buf[i] = v;
        mx = fmaxf(mx, v);
    }
    red[tid] = mx; __syncthreads();
    for (int s = 128; s > 0; s >>= 1) {
        if (tid < s) red[tid] = fmaxf(red[tid], red[tid+s]);
        __syncthreads();
    }
    mx = red[0];
    __syncthreads();
    float sum = 0.f;
    for (int i = tid; i < NN; i += 256) {
        float e = fexp(buf[i] - mx);
        buf[i] = e;
        sum += e;
    }
    red[tid] = sum; __syncthreads();
    for (int s = 128; s > 0; s >>= 1) {
        if (tid < s) red[tid] += red[tid+s];
        __syncthreads();
    }
    float inv = 1.0f / red[0];
    for (int i = tid; i < NN; i += 256)
        g_shi[(size_t)row*NN + i] = __float2half_rn(buf[i] * inv);
}

// ---------------- per-node weights, tiled ----------------
__global__ void __launch_bounds__(256) k_mkW2(const float* __restrict__ E,
                                              const float* __restrict__ pool,
                                              int per_e, float* __restrict__ W) {
    __shared__ __align__(16) float Es[16][128];
    __shared__ __align__(16) float Ps[16][128];
    int tid = threadIdx.x;
    int j0 = blockIdx.x*128, m0 = blockIdx.y*128;
    {
        int r = tid >> 1, e0 = (tid & 1)*8;
        float4 a = *(const float4*)&E[(size_t)(m0+r)*EMB + e0];
        float4 b = *(const float4*)&E[(size_t)(m0+r)*EMB + e0 + 4];
        Es[e0+0][r]=a.x; Es[e0+1][r]=a.y; Es[e0+2][r]=a.z; Es[e0+3][r]=a.w;
        Es[e0+4][r]=b.x; Es[e0+5][r]=b.y; Es[e0+6][r]=b.z; Es[e0+7][r]=b.w;
    }
    {
        int e = tid >> 4, c0 = (tid & 15)*8;
        float4 a = *(const float4*)&pool[(size_t)e*per_e + j0 + c0];
        float4 b = *(const float4*)&pool[(size_t)e*per_e + j0 + c0 + 4];
        *(float4*)&Ps[e][c0]   = a;
        *(float4*)&Ps[e][c0+4] = b;
    }
    __syncthreads();
    int row0 = (tid/16)*8, col0 = (tid%16)*8;
    float acc[8][8] = {};
#pragma unroll
    for (int k = 0; k < 16; k++) {
        float av[8], bv[8];
        float4 t;
        t = *(const float4*)&Es[k][row0];   av[0]=t.x; av[1]=t.y; av[2]=t.z; av[3]=t.w;
        t = *(const float4*)&Es[k][row0+4]; av[4]=t.x; av[5]=t.y; av[6]=t.z; av[7]=t.w;
        t = *(const float4*)&Ps[k][col0];   bv[0]=t.x; bv[1]=t.y; bv[2]=t.z; bv[3]=t.w;
        t = *(const float4*)&Ps[k][col0+4]; bv[4]=t.x; bv[5]=t.y; bv[6]=t.z; bv[7]=t.w;
#pragma unroll
        for (int i = 0; i < 8; i++)
#pragma unroll
            for (int j = 0; j < 8; j++) acc[i][j] += av[i]*bv[j];
    }
#pragma unroll
    for (int i = 0; i < 8; i++) {
        size_t ro = (size_t)(m0 + row0 + i)*per_e + j0 + col0;
        *(float4*)&W[ro]   = make_float4(acc[i][0], acc[i][1], acc[i][2], acc[i][3]);
        *(float4*)&W[ro+4] = make_float4(acc[i][4], acc[i][5], acc[i][6], acc[i][7]);
    }
}

// ---------------- concat ----------------
__global__ void k_concat(const float* __restrict__ x, const float* __restrict__ state) {
    int idx = blockIdx.x*256 + threadIdx.x;
    if (idx >= NN*XCOLS) return;
    int n = idx / XCOLS;
    int rem = idx % XCOLS;
    int b = rem / DIN, i = rem % DIN;
    float v;
    if (i < 2) v = x[((size_t)b*NN + n)*2 + i];
    else       v = state[((size_t)b*NN + n)*DD + (i-2)];
    g_inpT[idx] = v;
    __half hi = __float2half_rn(v);
    size_t pidx = (size_t)n*XPAD + rem;
    g_xinhi[pidx] = hi;
    if (i < 2) {
        g_candT[idx] = v;
        g_xcahi[pidx] = hi;
    }
}

// ---------------- xg = S @ X on HMMA (single pass) ----------------
#define SX_NSTG 3
#define SX_STAGE 16384
__global__ void __launch_bounds__(256, 2) k_sx_mma(int which) {
    extern __shared__ __align__(16) __half dsm[];
    const __half* Bhi = which ? g_xcahi : g_xinhi;
    float* C = which ? g_xg2T : g_xg1T;

    const int tid = threadIdx.x;
    const int n0 = blockIdx.x*128;
    const int m0 = blockIdx.y*128;
    uint32_t su = s2u(dsm);

    const int rowA = tid >> 1, ap0 = (tid & 1)*2;
    const int rowB = tid >> 3, bp0 = (tid & 7)*2;
    const size_t aRow = (size_t)(m0 + rowA)*NN;
    uint32_t dA[2], dB[2];
#pragma unroll
    for (int t = 0; t < 2; t++) {
        int ch = ap0 + t;
        dA[t] = rowA*64 + ((ch ^ ((rowA>>1)&3)) << 4);
        int cb = bp0 + t;
        dB[t] = 8192 + rowB*256 + ((cb ^ (rowB&7)) << 4);
    }

    auto issue = [&](int c, int s) {
        uint32_t base = su + s*SX_STAGE;   // stage: Shi 0 | X 8192
#pragma unroll
        for (int t = 0; t < 2; t++)
            cp16(base + dA[t], g_shi + aRow + c*32 + (ap0+t)*8);
#pragma unroll
        for (int t = 0; t < 2; t++) {
            int cb = bp0 + t;
            size_t bo = (size_t)(c*32 + rowB)*XPAD + n0 + cb*8;
            cp16(base + dB[t], Bhi + bo);
        }
        cpcommit();
    };

    const int lane = tid & 31, wid = tid >> 5;
    const int wm = (wid & 1)*64, wn = (wid >> 1)*32;
    const int frow = ((lane>>3)&1)*8 + (lane&7);
    const int fch  = lane >> 4;

    float acc[4][4][4] = {};
    issue(0, 0); issue(1, 1);
    const int NC = NN/32;
    for (int c = 0; c < NC; c++) {
        int s = c % SX_NSTG;
        if (c + 1 < NC) asm volatile("cp.async.wait_group 1;" ::: "memory");
        else            asm volatile("cp.async.wait_group 0;" ::: "memory");
        __syncthreads();
        if (c + 2 < NC) issue(c + 2, (c + 2) % SX_NSTG);
        uint32_t base = su + s*SX_STAGE;
#pragma unroll
        for (int ks = 0; ks < 2; ks++) {
            uint32_t af[4][4], bh[2][4];
#pragma unroll
            for (int i = 0; i < 4; i++) {
                int row = wm + i*16 + frow;
                int ch = 2*ks + fch;
                ldsm4(af[i], base + row*64 + ((ch ^ ((row>>1)&3)) << 4));
            }
#pragma unroll
            for (int jj = 0; jj < 2; jj++) {
                int krow = ks*16 + frow;
                int ch = (wn >> 3) + jj*2 + fch;
                ldsm4t(bh[jj], base + 8192 + krow*256 + ((ch ^ (krow&7)) << 4));
            }
#pragma unroll
            for (int i = 0; i < 4; i++)
#pragma unroll
                for (int j = 0; j < 4; j++) {
                    int jj = j >> 1, sb = (j & 1)*2;
                    mma16816(acc[i][j], af[i], bh[jj][sb], bh[jj][sb+1]);
                }
        }
    }
    const int r = lane >> 2, cq = (lane & 3)*2;
#pragma unroll
    for (int i = 0; i < 4; i++) {
        int r0 = m0 + wm + i*16 + r;
#pragma unroll
        for (int j = 0; j < 4; j++) {
            int cc = n0 + wn + j*8 + cq;
            *(float2*)&C[(size_t)r0*XPAD + cc]     = make_float2(acc[i][j][0], acc[i][j][1]);
            *(float2*)&C[(size_t)(r0+8)*XPAD + cc] = make_float2(acc[i][j][2], acc[i][j][3]);
        }
    }
}

// ---------------- gate apply ----------------
__global__ void k_gate_apply(const float* __restrict__ E, const float* __restrict__ gate_b,
                             const float* __restrict__ state) {
    int n = blockIdx.x;
    int o = threadIdx.x;
    __shared__ float Xs[BB][2*DIN];
    __shared__ float Es[16];
    if (o < 16) Es[o] = E[(size_t)n*EMB + o];
    for (int idx = o; idx < BB*2*DIN; idx += 128) {
        int bb = idx / (2*DIN), i = idx % (2*DIN);
        float v = (i < DIN) ? g_inpT[(size_t)n*XCOLS + bb*DIN + i]
                            : g_xg1T[(size_t)n*XPAD + bb*DIN + (i - DIN)];
        Xs[bb][i] = v;
    }
    __syncthreads();
    float bias = 0.f;
#pragma unroll
    for (int e = 0; e < 16; e++) bias += Es[e] * gate_b[e*OG + o];
    float acc[BB];
#pragma unroll
    for (int bb = 0; bb < BB; bb++) acc[bb] = bias;
    const float* Wn = g_Wg + (size_t)n*(2*DIN*OG);
    for (int i = 0; i < 2*DIN; i++) {
        float w = Wn[(size_t)i*OG + o];
#pragma unroll
        for (int bb = 0; bb < BB; bb++) acc[bb] += Xs[bb][i] * w;
    }
#pragma unroll
    for (int bb = 0; bb < BB; bb++) {
        float v = 1.0f / (1.0f + __expf(-acc[bb]));
        if (o < DD) {
            float st = state[((size_t)bb*NN + n)*DD + o];
            float zs = v * st;
            g_candT[(size_t)n*XCOLS + bb*DIN + 2 + o] = zs;
            g_xcahi[(size_t)n*XPAD + bb*DIN + 2 + o] = __float2half_rn(zs);
        } else {
            g_r[((size_t)bb*NN + n)*DD + (o - DD)] = v;
        }
    }
}

// ---------------- update apply: h, h16, out base 0.8h ----------------
__global__ void k_upd_apply(const float* __restrict__ E, const float* __restrict__ upd_b,
                            const float* __restrict__ state, float* __restrict__ out) {
    int n = blockIdx.x;
    int o = threadIdx.x;
    __shared__ float Xs[BB][2*DIN];
    __shared__ float Es[16];
    if (o < 16) Es[o] = E[(size_t)n*EMB + o];
    for (int idx = o; idx < BB*2*DIN; idx += 64) {
        int bb = idx / (2*DIN), i = idx % (2*DIN);
        Xs[bb][i] = (i < DIN) ? g_candT[(size_t)n*XCOLS + bb*DIN + i]
                              : g_xg2T[(size_t)n*XPAD + bb*DIN + (i - DIN)];
    }
    __syncthreads();
    float bias = 0.f;
#pragma unroll
    for (int e = 0; e < 16; e++) bias += Es[e] * upd_b[e*OU + o];
    float acc[BB];
#pragma unroll
    for (int bb = 0; bb < BB; bb++) acc[bb] = bias;
    const float* Wn = g_Wu + (size_t)n*(2*DIN*OU);
    for (int i = 0; i < 2*DIN; i++) {
        float w = Wn[(size_t)i*OU + o];
#pragma unroll
        for (int bb = 0; bb < BB; bb++) acc[bb] += Xs[bb][i] * w;
    }
#pragma unroll
    for (int bb = 0; bb < BB; bb++) {
        float hc = tanhf(acc[bb]);
        size_t ix = ((size_t)bb*NN + n)*DD + o;
        float r = g_r[ix];
        float hv = r * state[ix] + (1.0f - r) * hc;
        g_h[ix] = hv;
        g_h16[ix] = __float2half_rn(hv);
        out[ix] = 0.8f * hv;
    }
}

// ---------------- HHT on HMMA: g_ac/g_ad = mask(.) * (h16 @ h16^T) ----------------
__global__ void __launch_bounds__(256, 2) k_hht_mma() {
    __shared__ __align__(16) __half sA[128*64];
    __shared__ __align__(16) __half sB[128*64];
    const int tid = threadIdx.x;
    const int b = blockIdx.z, m0 = blockIdx.y*128, n0 = blockIdx.x*128;
    uint32_t aU = s2u(sA), bU = s2u(sB);

    const int row = tid >> 1, c0 = (tid & 1)*4;
#pragma unroll
    for (int t = 0; t < 4; t++) {
        int ch = c0 + t;
        uint32_t off = row*128 + ((ch ^ (row&7)) << 4);
        cp16(aU + off, g_h16 + ((size_t)b*NN + m0 + row)*64 + ch*8);
        cp16(bU + off, g_h16 + ((size_t)b*NN + n0 + row)*64 + ch*8);
    }
    cpcommit();
    asm volatile("cp.async.wait_group 0;" ::: "memory");
    __syncthreads();

    const int lane = tid & 31, wid = tid >> 5;
    const int wm = (wid & 1)*64, wn = (wid >> 1)*32;
    const int frow = ((lane>>3)&1)*8 + (lane&7);
    const int fch  = lane >> 4;

    float acc[4][4][4] = {};
#pragma unroll
    for (int ks = 0; ks < 4; ks++) {
        uint32_t af[4][4], bf[2][4];
#pragma unroll
        for (int i = 0; i < 4; i++) {
            int rr = wm + i*16 + frow;
            int ch = 2*ks + fch;
            ldsm4(af[i], aU + rr*128 + ((ch ^ (rr&7)) << 4));
        }
#pragma unroll
        for (int jj = 0; jj < 2; jj++) {
            int rr = wn + jj*16 + frow;
            int ch = 2*ks + fch;
            ldsm4(bf[jj], bU + rr*128 + ((ch ^ (rr&7)) << 4));
        }
#pragma unroll
        for (int i = 0; i < 4; i++)
#pragma unroll
            for (int j = 0; j < 4; j++) {
                int jj = j >> 1, sb = j & 1;
                mma16816(acc[i][j], af[i], bf[jj][sb], bf[jj][sb+2]);
            }
    }
    const int r = lane >> 2, cq = (lane & 3)*2;
#pragma unroll
    for (int i = 0; i < 4; i++) {
        int rbase = m0 + wm + i*16 + r;
#pragma unroll
        for (int j = 0; j < 4; j++) {
            int cc = n0 + wn + j*8 + cq;
#pragma unroll
            for (int hh = 0; hh < 2; hh++) {
                int rr = rbase + hh*8;
                uchar2 mk = *(const uchar2*)&g_mask[(size_t)rr*NN + cc];
                float v0 = acc[i][j][hh*2+0], v1 = acc[i][j][hh*2+1];
                __half2 hc = __floats2half2_rn(mk.x == 1 ? v0 : 0.f, mk.y == 1 ? v1 : 0.f);
                __half2 hd = __floats2half2_rn(mk.x == 2 ? v0 : 0.f, mk.y == 2 ? v1 : 0.f);
                *(__half2*)&g_ac[((size_t)b*NN + rr)*NN + cc] = hc;
                *(__half2*)&g_ad[((size_t)b*NN + rr)*NN + cc] = hd;
            }
        }
    }
}

// ---------------- W (fp32 [k][n]) -> transposed fp16 Wt[n][k], both ----------------
__global__ void k_convW(const float* __restrict__ Wc, const float* __restrict__ Wd) {
    __shared__ float t[32][33];
    int tx = threadIdx.x, ty = threadIdx.y;
    int bx = blockIdx.x*32, by = blockIdx.y*32;
    const float* W = blockIdx.z ? Wd : Wc;
    __half* Wt = blockIdx.z ? g_wd : g_wc;
    for (int j = 0; j < 32; j += 8)
        t[ty+j][tx] = W[(size_t)(by+ty+j)*NN + bx+tx];
    __syncthreads();
    for (int j = 0; j < 32; j += 8) {
        float v = t[tx][ty+j];
        Wt[(size_t)(bx+ty+j)*NN + by+tx] = __float2half_rn(v);
    }
}

// ---------------- big GEMM: both branches, 256x128 CTA, warp tile 64x64 ----------------
#define BG_NSTG 3
__global__ void __launch_bounds__(256, 1) k_biggemm_mma() {
    __shared__ __align__(16) __half sA[BG_NSTG][256*32];
    __shared__ __align__(16) __half sW[BG_NSTG][128*32];
    __shared__ float smax[2][256];
    const int tid = threadIdx.x;
    const int bz = blockIdx.z, b = bz & 15, br = bz >> 4;
    const int m0 = blockIdx.y*256, n0 = blockIdx.x*128;
    const __half* Am = ((br == 0) ? g_ac : g_ad) + (size_t)b*NN*NN;
    const __half* Wt = (br == 0) ? g_wc : g_wd;
    uint32_t aU = s2u(sA), wU = s2u(sW);

    const int rowA = tid >> 1, ap0 = (tid & 1)*2;
    const int rowW = tid >> 2, chW = tid & 3;
    const size_t aRow0 = (size_t)(m0 + rowA)*NN;
    const size_t aRow1 = (size_t)(m0 + rowA + 128)*NN;
    const size_t wRow0 = (size_t)(n0 + rowW)*NN;
    const size_t wRow1 = (size_t)(n0 + rowW + 64)*NN;
    uint32_t dA[2];
#pragma unroll
    for (int t = 0; t < 2; t++) {
        int ch = ap0 + t;
        dA[t] = rowA*64 + ((ch ^ ((rowA>>1)&3)) << 4);
    }
    const uint32_t dW = rowW*64 + ((chW ^ ((rowW>>1)&3)) << 4);

    auto issue = [&](int c, int s) {
#pragma unroll
        for (int t = 0; t < 2; t++) {
            cp16(aU + s*16384 + dA[t],            Am + aRow0 + c*32 + (ap0+t)*8);
            cp16(aU + s*16384 + dA[t] + 128*64,   Am + aRow1 + c*32 + (ap0+t)*8);
        }
        cp16(wU + s*8192 + dW,           Wt + wRow0 + c*32 + chW*8);
        cp16(wU + s*8192 + dW + 64*64,   Wt + wRow1 + c*32 + chW*8);
        cpcommit();
    };

    const int lane = tid & 31, wid = tid >> 5;
    const int wm = (wid & 3)*64;
    const int wn = (wid >> 2)*64;
    const int frow = ((lane>>3)&1)*8 + (lane&7);
    const int fch  = lane >> 4;

    float acc[4][8][4] = {};
    issue(0, 0); issue(1, 1);
    const int NC = NN/32;
    for (int c = 0; c < NC; c++) {
        int s = c % BG_NSTG;
        if (c + 1 < NC) asm volatile("cp.async.wait_group 1;" ::: "memory");
        else            asm volatile("cp.async.wait_group 0;" ::: "memory");
        __syncthreads();
        if (c + 2 < NC) issue(c + 2, (c + 2) % BG_NSTG);
        uint32_t aB = aU + s*16384, wB = wU + s*8192;
#pragma unroll
        for (int ks = 0; ks < 2; ks++) {
            uint32_t af[4][4], bf[4][4];
#pragma unroll
            for (int i = 0; i < 4; i++) {
                int row = wm + i*16 + frow;
                int ch = 2*ks + fch;
                ldsm4(af[i], aB + row*64 + ((ch ^ ((row>>1)&3)) << 4));
            }
#pragma unroll
            for (int jj = 0; jj < 4; jj++) {
                int row = wn + jj*16 + frow;
                int ch = 2*ks + fch;
                ldsm4(bf[jj], wB + row*64 + ((ch ^ ((row>>1)&3)) << 4));
            }
#pragma unroll
            for (int i = 0; i < 4; i++)
#pragma unroll
                for (int j = 0; j < 8; j++) {
                    int jj = j >> 1, sb = j & 1;
                    mma16816(acc[i][j], af[i], bf[jj][sb], bf[jj][sb+2]);
                }
        }
    }
    __half* C = g_deg16 + (((size_t)br*BB + b)*NN)*NN;
    const int r = lane >> 2, cq = (lane & 3)*2;
#pragma unroll
    for (int i = 0; i < 4; i++) {
#pragma unroll
        for (int hh = 0; hh < 2; hh++) {
            int r0 = m0 + wm + i*16 + hh*8 + r;
            float m = -1e30f;
#pragma unroll
            for (int j = 0; j < 8; j++) {
                float v0 = acc[i][j][hh*2+0], v1 = acc[i][j][hh*2+1];
                m = fmaxf(m, fmaxf(v0, v1));
                int cc = n0 + wn + j*8 + cq;
                *(__half2*)&C[(size_t)r0*NN + cc] = __floats2half2_rn(v0, v1);
            }
            m = fmaxf(m, __shfl_xor_sync(0xffffffff, m, 1));
            m = fmaxf(m, __shfl_xor_sync(0xffffffff, m, 2));
            if ((lane & 3) == 0) smax[wid >> 2][wm + i*16 + hh*8 + r] = m;
        }
    }
    __syncthreads();
    if (tid < 256) {
        float m2 = fmaxf(smax[0][tid], smax[1][tid]);
        g_pmax[(((size_t)br*BB + b)*16 + blockIdx.x)*NN + m0 + tid] = m2;
    }
}

// ---------------- fused softmax + deg@h: exp applied in smem, row sum in-kernel ----------------
#define DH_NSTG 3
__global__ void __launch_bounds__(256, 2) k_deg_h_mma(float* __restrict__ out) {
    __shared__ __align__(16) __half sA[DH_NSTG][128*32];
    __shared__ __align__(16) __half sB[DH_NSTG][32*64];
    __shared__ float mxs[128];
    __shared__ float lsum[256];
    const int tid = threadIdx.x;
    const int bz = blockIdx.z, b = bz & 15, br = bz >> 4;
    const int m0 = blockIdx.y*128;
    const float alpha = (br == 0) ? -0.1f : 0.1f;
    const __half* Ap = g_deg16 + (((size_t)br*BB + b)*NN)*NN;
    const __half* Hp = g_h16 + (size_t)b*NN*DD;
    uint32_t aU = s2u(sA), bU = s2u(sB);
    char* aC = (char*)sA;

    // row max from per-CTA partials
    if (tid < 128) {
        float mx = -1e30f;
#pragma unroll
        for (int nt = 0; nt < 16; nt++)
            mx = fmaxf(mx, g_pmax[(((size_t)br*BB + b)*16 + nt)*NN + m0 + tid]);
        mxs[tid] = mx;
    }
    __syncthreads();

    const int rowA = tid >> 1, ap0 = (tid & 1)*2;
    const float mxr = mxs[rowA];
    const size_t aRow = (size_t)(m0 + rowA)*NN;
    uint32_t dA[2];
#pragma unroll
    for (int t = 0; t < 2; t++) {
        int ch = ap0 + t;
        dA[t] = rowA*64 + ((ch ^ ((rowA>>1)&3)) << 4);
    }
    const int rowB = tid >> 3, chB = tid & 7;
    const uint32_t dB = rowB*128 + ((chB ^ (rowB&7)) << 4);

    auto issue = [&](int c, int s) {
#pragma unroll
        for (int t = 0; t < 2; t++)
            cp16(aU + s*8192 + dA[t], Ap + aRow + c*32 + (ap0+t)*8);
        cp16(bU + s*4096 + dB, Hp + (size_t)(c*32 + rowB)*DD + chB*8);
        cpcommit();
    };

    const int lane = tid & 31, wid = tid >> 5;
    const int wm = (wid & 3)*32;
    const int wn = (wid >> 2)*32;
    const int frow = ((lane>>3)&1)*8 + (lane&7);
    const int fch  = lane >> 4;

    float acc[2][4][4] = {};
    float lacc = 0.f;
    issue(0, 0); issue(1, 1);
    const int NC = NN/32;
    for (int c = 0; c < NC; c++) {
        int s = c % DH_NSTG;
        if (c + 1 < NC) asm volatile("cp.async.wait_group 1;" ::: "memory");
        else            asm volatile("cp.async.wait_group 0;" ::: "memory");
        __syncthreads();
        if (c + 2 < NC) issue(c + 2, (c + 2) % DH_NSTG);

        // transform: exp(logit - rowmax) in place, accumulate row-sum partial
#pragma unroll
        for (int t = 0; t < 2; t++) {
            uint4* p = (uint4*)(aC + s*8192 + dA[t]);
            uint4 v = *p;
            __half2* hv = (__half2*)&v;
#pragma unroll
            for (int q = 0; q < 4; q++) {
                float2 f = __half22float2(hv[q]);
                f.x = fexp(f.x - mxr);
                f.y = fexp(f.y - mxr);
                lacc += f.x + f.y;
                hv[q] = __floats2half2_rn(f.x, f.y);
            }
            *p = v;
        }
        __syncthreads();

        uint32_t aB = aU + s*8192, bBs = bU + s*4096;
#pragma unroll
        for (int ks = 0; ks < 2; ks++) {
            uint32_t af[2][4], bt[2][4];
#pragma unroll
            for (int i = 0; i < 2; i++) {
                int row = wm + i*16 + frow;
                int ch = 2*ks + fch;
                ldsm4(af[i], aB + row*64 + ((ch ^ ((row>>1)&3)) << 4));
            }
#pragma unroll
            for (int jj = 0; jj < 2; jj++) {
                int krow = ks*16 + frow;
                int ch = (wn >> 3) + jj*2 + fch;
                ldsm4t(bt[jj], bBs + krow*128 + ((ch ^ (krow&7)) << 4));
            }
#pragma unroll
            for (int i = 0; i < 2; i++)
#pragma unroll
                for (int j = 0; j < 4; j++) {
                    int jj = j >> 1, sb = (j & 1)*2;
                    mma16816(acc[i][j], af[i], bt[jj][sb], bt[jj][sb+1]);
                }
        }
    }
    lsum[tid] = lacc;
    __syncthreads();

    const int r = lane >> 2, cq = (lane & 3)*2;
#pragma unroll
    for (int i = 0; i < 2; i++) {
#pragma unroll
        for (int hh = 0; hh < 2; hh++) {
            int lr = wm + i*16 + hh*8 + r;
            int r0 = m0 + lr;
            float l = lsum[2*lr] + lsum[2*lr + 1];
            float sc = alpha / l;
#pragma unroll
            for (int j = 0; j < 4; j++) {
                int cc = wn + j*8 + cq;
                size_t ix = ((size_t)b*NN + r0)*DD + cc;
                atomicAdd(&out[ix],   sc * acc[i][j][hh*2+0]);
                atomicAdd(&out[ix+1], sc * acc[i][j][hh*2+1]);
            }
        }
    }
}

// ---------------- launch ----------------
extern "C" void kernel_launch(void* const* d_in, const int* in_sizes, int n_in,
                              void* d_out, int out_size) {
    const float* x       = (const float*)d_in[0];
    const float* state   = (const float*)d_in[1];
    const float* E       = (const float*)d_in[2];
    const float* Wc      = (const float*)d_in[3];
    const float* Wd      = (const float*)d_in[4];
    const float* gate_w  = (const float*)d_in[5];
    const float* gate_b  = (const float*)d_in[6];
    const float* upd_w   = (const float*)d_in[7];
    const float* upd_b   = (const float*)d_in[8];
    float* out = (float*)d_out;

    const int SX_SMEM = SX_NSTG * SX_STAGE;   // 48KB
    cudaFuncSetAttribute(k_sx_mma, cudaFuncAttributeMaxDynamicSharedMemorySize, SX_SMEM);

    float* d_Wg; cudaGetSymbolAddress((void**)&d_Wg, g_Wg);
    float* d_Wu; cudaGetSymbolAddress((void**)&d_Wu, g_Wu);

    // adjacency + supports + sign mask
    k_embed_outer<<<dim3(128,128), dim3(16,16)>>>(E);
    k_srowsoftmax<<<NN, 256>>>();

    // per-node weights + weight transposes
    k_mkW2<<<dim3((2*DIN*OG)/128, NN/128), 256>>>(E, gate_w, 2*DIN*OG, d_Wg);
    k_mkW2<<<dim3((2*DIN*OU)/128, NN/128), 256>>>(E, upd_w,  2*DIN*OU, d_Wu);
    k_convW<<<dim3(64,64,2), dim3(32,8)>>>(Wc, Wd);

    // gate path
    k_concat<<<(NN*XCOLS + 255)/256, 256>>>(x, state);
    k_sx_mma<<<dim3(XPAD/128, NN/128), 256, SX_SMEM>>>(0);
    k_gate_apply<<<NN, 128>>>(E, gate_b, state);

    // update path
    k_sx_mma<<<dim3(XPAD/128, NN/128), 256, SX_SMEM>>>(1);
    k_upd_apply<<<NN, 64>>>(E, upd_b, state, out);

    // HHT -> masked fp16 (both branches)
    k_hht_mma<<<dim3(16,16,16), 256>>>();

    // both-branch big GEMM (raw fp16 logits + row-max partials)
    k_biggemm_mma<<<dim3(16, 8, 32), 256>>>();

    // fused softmax + deg@h, both branches, atomicAdd onto 0.8h base
    k_deg_h_mma<<<dim3(1, 16, 32), 256>>>(out);
}